// round 2
// baseline (speedup 1.0000x reference)
#include <cuda_runtime.h>
#include <cstdint>

#define N_NODES 50000
#define N_EDGES 800000
#define D_IN    256
#define D_HID   256
#define D_OUT   128

// ---- scratch (no allocations allowed) ----
__device__ float g_agg1[N_NODES * D_HID];   // layer-1 sum aggregate (scaled to mean at GEMM load)
__device__ float g_h   [N_NODES * D_HID];   // layer-1 output
__device__ float g_y2  [N_NODES * D_OUT];   // h @ W2_l  (aggregated over edges)
__device__ float g_z2  [N_NODES * D_OUT];   // h @ W2_r + b2
__device__ float g_agg2[N_NODES * D_OUT];   // layer-2 sum aggregate
__device__ int   g_deg [N_NODES];
__device__ float g_rdeg[N_NODES];

__device__ __forceinline__ int clampi(int v) {
    return min(max(v, 0), N_NODES - 1);
}

__device__ __forceinline__ void red4(float4* p, float4 v) {
    asm volatile("red.global.add.v4.f32 [%0], {%1,%2,%3,%4};"
                 :: "l"(p), "f"(v.x), "f"(v.y), "f"(v.z), "f"(v.w) : "memory");
}

// ---- zero accumulators + degree ----
__global__ void zero_kernel() {
    long tid    = (long)blockIdx.x * blockDim.x + threadIdx.x;
    long stride = (long)gridDim.x * blockDim.x;
    float4 z = make_float4(0.f, 0.f, 0.f, 0.f);
    const long n1 = (long)N_NODES * D_HID / 4;
    for (long i = tid; i < n1; i += stride) ((float4*)g_agg1)[i] = z;
    const long n2 = (long)N_NODES * D_OUT / 4;
    for (long i = tid; i < n2; i += stride) ((float4*)g_agg2)[i] = z;
    for (long i = tid; i < N_NODES; i += stride) g_deg[i] = 0;
}

__global__ void degree_kernel(const int* __restrict__ ei) {
    int e = blockIdx.x * blockDim.x + threadIdx.x;
    if (e < N_EDGES) atomicAdd(&g_deg[clampi(ei[N_EDGES + e])], 1);
}

__global__ void rdeg_kernel() {
    int i = blockIdx.x * blockDim.x + threadIdx.x;
    if (i < N_NODES) g_rdeg[i] = 1.0f / fmaxf((float)g_deg[i], 1.0f);
}

// ---- layer-1 scatter: agg1[dst] += x[src]  (one warp per edge, 256 floats) ----
__global__ void scatter1_kernel(const float* __restrict__ x,
                                const int* __restrict__ ei) {
    int warp = (int)((blockIdx.x * (long)blockDim.x + threadIdx.x) >> 5);
    int lane = threadIdx.x & 31;
    if (warp >= N_EDGES) return;
    int src = clampi(ei[warp]);
    int dst = clampi(ei[N_EDGES + warp]);
    const float4* xs = (const float4*)(x + (long)src * D_IN);
    float4*       ap = (float4*)(g_agg1 + (long)dst * D_IN);
    float4 v0 = xs[lane];
    float4 v1 = xs[lane + 32];
    red4(ap + lane, v0);
    red4(ap + lane + 32, v1);
}

// ---- layer-2 scatter: agg2[dst] += y2[src]  (one warp per edge, 128 floats) ----
__global__ void scatter2_kernel(const int* __restrict__ ei) {
    int warp = (int)((blockIdx.x * (long)blockDim.x + threadIdx.x) >> 5);
    int lane = threadIdx.x & 31;
    if (warp >= N_EDGES) return;
    int src = clampi(ei[warp]);
    int dst = clampi(ei[N_EDGES + warp]);
    const float4* ys = (const float4*)(g_y2 + (long)src * D_OUT);
    float4*       ap = (float4*)(g_agg2 + (long)dst * D_OUT);
    red4(ap + lane, ys[lane]);
}

// ---- GEMM tiles: 128x128 block, 8x8 per thread, 256 threads, BK=16 ----
#define BM 128
#define BN 128
#define BK 16

// h = relu(mean1 @ W1_l + x @ W1_r + b1); mean1 = agg1 * rdeg (scaled at load)
__global__ __launch_bounds__(256, 2)
void gemm1_kernel(const float* __restrict__ x,
                  const float* __restrict__ W1l,
                  const float* __restrict__ W1r,
                  const float* __restrict__ b1) {
    __shared__ float As[BK][BM];
    __shared__ float Bs[BK][BN];
    float acc[8][8];
#pragma unroll
    for (int i = 0; i < 8; i++)
#pragma unroll
        for (int j = 0; j < 8; j++) acc[i][j] = 0.f;

    int tid = threadIdx.x;
    int tx = tid & 15, ty = tid >> 4;
    int row0 = blockIdx.x * BM;
    int col0 = blockIdx.y * BN;

    int ar = tid >> 1;           // 0..127 (A tile row)
    int ac = (tid & 1) * 8;      // 0 or 8 (A tile k-offset)
    int arow = row0 + ar;
    bool avalid = arow < N_NODES;
    float rdeg = avalid ? g_rdeg[arow] : 0.f;

    int bi = tid * 2;            // B tile float4 index
    int br = bi >> 5;            // 0..15
    int bc = bi & 31;            // 0..30 even

    for (int pass = 0; pass < 2; ++pass) {
        const float* A = pass ? x : g_agg1;
        const float* B = pass ? W1r : W1l;
        float asc = pass ? 1.0f : rdeg;
        for (int k0 = 0; k0 < D_IN; k0 += BK) {
            float4 a0 = make_float4(0.f,0.f,0.f,0.f), a1 = a0;
            if (avalid) {
                const float4* apx = (const float4*)(A + (long)arow * D_IN + k0 + ac);
                a0 = apx[0]; a1 = apx[1];
            }
            a0.x *= asc; a0.y *= asc; a0.z *= asc; a0.w *= asc;
            a1.x *= asc; a1.y *= asc; a1.z *= asc; a1.w *= asc;
            const float4* bp = (const float4*)(B + (long)(k0 + br) * 256 + col0) + bc;
            float4 b0 = bp[0], b1v = bp[1];
            __syncthreads();
            As[ac + 0][ar] = a0.x; As[ac + 1][ar] = a0.y;
            As[ac + 2][ar] = a0.z; As[ac + 3][ar] = a0.w;
            As[ac + 4][ar] = a1.x; As[ac + 5][ar] = a1.y;
            As[ac + 6][ar] = a1.z; As[ac + 7][ar] = a1.w;
            ((float4*)&Bs[br][0])[bc]     = b0;
            ((float4*)&Bs[br][0])[bc + 1] = b1v;
            __syncthreads();
#pragma unroll
            for (int kk = 0; kk < BK; kk++) {
                float a[8], b[8];
                *(float4*)&a[0] = *(const float4*)&As[kk][ty * 8];
                *(float4*)&a[4] = *(const float4*)&As[kk][ty * 8 + 4];
                *(float4*)&b[0] = *(const float4*)&Bs[kk][tx * 8];
                *(float4*)&b[4] = *(const float4*)&Bs[kk][tx * 8 + 4];
#pragma unroll
                for (int i = 0; i < 8; i++)
#pragma unroll
                    for (int j = 0; j < 8; j++) acc[i][j] += a[i] * b[j];
            }
        }
    }

    int ccol = col0 + tx * 8;
    float bias[8];
#pragma unroll
    for (int j = 0; j < 8; j++) bias[j] = b1[ccol + j];
#pragma unroll
    for (int i = 0; i < 8; i++) {
        int r = row0 + ty * 8 + i;
        if (r < N_NODES) {
            float4 o0, o1;
            o0.x = fmaxf(acc[i][0] + bias[0], 0.f);
            o0.y = fmaxf(acc[i][1] + bias[1], 0.f);
            o0.z = fmaxf(acc[i][2] + bias[2], 0.f);
            o0.w = fmaxf(acc[i][3] + bias[3], 0.f);
            o1.x = fmaxf(acc[i][4] + bias[4], 0.f);
            o1.y = fmaxf(acc[i][5] + bias[5], 0.f);
            o1.z = fmaxf(acc[i][6] + bias[6], 0.f);
            o1.w = fmaxf(acc[i][7] + bias[7], 0.f);
            float4* op = (float4*)(g_h + (long)r * D_HID + ccol);
            op[0] = o0; op[1] = o1;
        }
    }
}

// blockIdx.y==0: y2 = h @ W2_l ; blockIdx.y==1: z2 = h @ W2_r + b2
__global__ __launch_bounds__(256, 2)
void gemm2_kernel(const float* __restrict__ W2l,
                  const float* __restrict__ W2r,
                  const float* __restrict__ b2) {
    __shared__ float As[BK][BM];
    __shared__ float Bs[BK][BN];
    float acc[8][8];
#pragma unroll
    for (int i = 0; i < 8; i++)
#pragma unroll
        for (int j = 0; j < 8; j++) acc[i][j] = 0.f;

    bool second = (blockIdx.y == 1);
    const float* B = second ? W2r : W2l;      // [256,128]
    float* C = second ? g_z2 : g_y2;          // [N,128]

    int tid = threadIdx.x;
    int tx = tid & 15, ty = tid >> 4;
    int row0 = blockIdx.x * BM;

    int ar = tid >> 1;
    int ac = (tid & 1) * 8;
    int arow = row0 + ar;
    bool avalid = arow < N_NODES;

    int bi = tid * 2;
    int br = bi >> 5;
    int bc = bi & 31;

    for (int k0 = 0; k0 < D_HID; k0 += BK) {
        float4 a0 = make_float4(0.f,0.f,0.f,0.f), a1 = a0;
        if (avalid) {
            const float4* apx = (const float4*)(g_h + (long)arow * D_HID + k0 + ac);
            a0 = apx[0]; a1 = apx[1];
        }
        const float4* bp = (const float4*)(B + (long)(k0 + br) * D_OUT) + bc;
        float4 b0 = bp[0], b1v = bp[1];
        __syncthreads();
        As[ac + 0][ar] = a0.x; As[ac + 1][ar] = a0.y;
        As[ac + 2][ar] = a0.z; As[ac + 3][ar] = a0.w;
        As[ac + 4][ar] = a1.x; As[ac + 5][ar] = a1.y;
        As[ac + 6][ar] = a1.z; As[ac + 7][ar] = a1.w;
        ((float4*)&Bs[br][0])[bc]     = b0;
        ((float4*)&Bs[br][0])[bc + 1] = b1v;
        __syncthreads();
#pragma unroll
        for (int kk = 0; kk < BK; kk++) {
            float a[8], b[8];
            *(float4*)&a[0] = *(const float4*)&As[kk][ty * 8];
            *(float4*)&a[4] = *(const float4*)&As[kk][ty * 8 + 4];
            *(float4*)&b[0] = *(const float4*)&Bs[kk][tx * 8];
            *(float4*)&b[4] = *(const float4*)&Bs[kk][tx * 8 + 4];
#pragma unroll
            for (int i = 0; i < 8; i++)
#pragma unroll
                for (int j = 0; j < 8; j++) acc[i][j] += a[i] * b[j];
        }
    }

    int ccol = tx * 8;
    float bias[8];
#pragma unroll
    for (int j = 0; j < 8; j++) bias[j] = second ? b2[ccol + j] : 0.f;
#pragma unroll
    for (int i = 0; i < 8; i++) {
        int r = row0 + ty * 8 + i;
        if (r < N_NODES) {
            float4 o0, o1;
            o0.x = acc[i][0] + bias[0];
            o0.y = acc[i][1] + bias[1];
            o0.z = acc[i][2] + bias[2];
            o0.w = acc[i][3] + bias[3];
            o1.x = acc[i][4] + bias[4];
            o1.y = acc[i][5] + bias[5];
            o1.z = acc[i][6] + bias[6];
            o1.w = acc[i][7] + bias[7];
            float4* op = (float4*)(C + (long)r * D_OUT + ccol);
            op[0] = o0; op[1] = o1;
        }
    }
}

// out = agg2 * rdeg + z2
__global__ void final_kernel(float* __restrict__ out) {
    long tid    = (long)blockIdx.x * blockDim.x + threadIdx.x;
    long stride = (long)gridDim.x * blockDim.x;
    const long n = (long)N_NODES * D_OUT / 4;
    for (long i = tid; i < n; i += stride) {
        int node = (int)(i >> 5);  // 128/4 = 32 float4 per node
        float r = g_rdeg[node];
        float4 a = ((const float4*)g_agg2)[i];
        float4 z = ((const float4*)g_z2)[i];
        float4 o;
        o.x = a.x * r + z.x;
        o.y = a.y * r + z.y;
        o.z = a.z * r + z.z;
        o.w = a.w * r + z.w;
        ((float4*)out)[i] = o;
    }
}

extern "C" void kernel_launch(void* const* d_in, const int* in_sizes, int n_in,
                              void* d_out, int out_size) {
    const float* x   = (const float*)d_in[0];
    const int*   ei  = (const int*)d_in[1];
    const float* W1l = (const float*)d_in[2];
    const float* b1  = (const float*)d_in[3];
    const float* W1r = (const float*)d_in[4];
    const float* W2l = (const float*)d_in[5];
    const float* b2  = (const float*)d_in[6];
    const float* W2r = (const float*)d_in[7];
    float* out = (float*)d_out;

    zero_kernel<<<1184, 256>>>();
    degree_kernel<<<(N_EDGES + 255) / 256, 256>>>(ei);
    rdeg_kernel<<<(N_NODES + 255) / 256, 256>>>();
    scatter1_kernel<<<(int)(((long)N_EDGES * 32 + 255) / 256), 256>>>(x, ei);

    dim3 g1((N_NODES + BM - 1) / BM, 2);
    gemm1_kernel<<<g1, 256>>>(x, W1l, W1r, b1);
    gemm2_kernel<<<g1, 256>>>(W2l, W2r, b2);

    scatter2_kernel<<<(int)(((long)N_EDGES * 32 + 255) / 256), 256>>>(ei);
    final_kernel<<<592, 256>>>(out);
}

// round 3
// speedup vs baseline: 1.0430x; 1.0430x over previous
#include <cuda_runtime.h>
#include <cuda_bf16.h>
#include <cstdint>

#define N_NODES 50000
#define N_EDGES 800000
#define D_IN    256
#define D_HID   256
#define D_OUT   128

// ---- scratch (no allocations allowed) ----
__device__ float g_agg1[N_NODES * D_HID];   // layer-1 sum aggregate
__device__ float g_h   [N_NODES * D_HID];   // layer-1 output
__device__ float g_y2  [N_NODES * D_OUT];   // h @ W2_l (then aggregated over edges)
__device__ float g_z2  [N_NODES * D_OUT];   // h @ W2_r + b2
__device__ float g_agg2[N_NODES * D_OUT];   // layer-2 sum aggregate
__device__ int   g_deg [N_NODES];
__device__ float g_rdeg[N_NODES];

__device__ __forceinline__ int clampi(int v) {
    return min(max(v, 0), N_NODES - 1);
}

__device__ __forceinline__ void red4(float4* p, float4 v) {
    asm volatile("red.global.add.v4.f32 [%0], {%1,%2,%3,%4};"
                 :: "l"(p), "f"(v.x), "f"(v.y), "f"(v.z), "f"(v.w) : "memory");
}

// ---- zero accumulators + degree ----
__global__ void zero_kernel() {
    long tid    = (long)blockIdx.x * blockDim.x + threadIdx.x;
    long stride = (long)gridDim.x * blockDim.x;
    float4 z = make_float4(0.f, 0.f, 0.f, 0.f);
    const long n1 = (long)N_NODES * D_HID / 4;
    for (long i = tid; i < n1; i += stride) ((float4*)g_agg1)[i] = z;
    const long n2 = (long)N_NODES * D_OUT / 4;
    for (long i = tid; i < n2; i += stride) ((float4*)g_agg2)[i] = z;
    for (long i = tid; i < N_NODES; i += stride) g_deg[i] = 0;
}

__global__ void degree_kernel(const int* __restrict__ ei) {
    int e = blockIdx.x * blockDim.x + threadIdx.x;
    if (e < N_EDGES) atomicAdd(&g_deg[clampi(ei[N_EDGES + e])], 1);
}

__global__ void rdeg_kernel() {
    int i = blockIdx.x * blockDim.x + threadIdx.x;
    if (i < N_NODES) g_rdeg[i] = 1.0f / fmaxf((float)g_deg[i], 1.0f);
}

// ---- layer-1 scatter: agg1[dst] += x[src] ----
__global__ void scatter1_kernel(const float* __restrict__ x,
                                const int* __restrict__ ei) {
    int warp = (int)((blockIdx.x * (long)blockDim.x + threadIdx.x) >> 5);
    int lane = threadIdx.x & 31;
    if (warp >= N_EDGES) return;
    int src = clampi(ei[warp]);
    int dst = clampi(ei[N_EDGES + warp]);
    const float4* xs = (const float4*)(x + (long)src * D_IN);
    float4*       ap = (float4*)(g_agg1 + (long)dst * D_IN);
    float4 v0 = xs[lane];
    float4 v1 = xs[lane + 32];
    red4(ap + lane, v0);
    red4(ap + lane + 32, v1);
}

// ---- layer-2 scatter: agg2[dst] += y2[src] ----
__global__ void scatter2_kernel(const int* __restrict__ ei) {
    int warp = (int)((blockIdx.x * (long)blockDim.x + threadIdx.x) >> 5);
    int lane = threadIdx.x & 31;
    if (warp >= N_EDGES) return;
    int src = clampi(ei[warp]);
    int dst = clampi(ei[N_EDGES + warp]);
    const float4* ys = (const float4*)(g_y2 + (long)src * D_OUT);
    float4*       ap = (float4*)(g_agg2 + (long)dst * D_OUT);
    red4(ap + lane, ys[lane]);
}

// ======================================================================
// Tensor-core GEMM: split-bf16 3-pass (Ah*Bh + Ah*Bl + Al*Bh), fp32 acc.
// Block tile 128x128, BK=32, 256 threads (8 warps, warp tile 32x64).
// smem rows padded to 40 bf16 (80B) -> ldmatrix conflict-free.
// ======================================================================

#define GBM 128
#define GBN 128
#define GBK 32
#define SPAD 40   // bf16 elements per smem row

struct GemmSmem {
    __nv_bfloat16 Ah[GBM][SPAD];
    __nv_bfloat16 Al[GBM][SPAD];
    __nv_bfloat16 Bh[GBN][SPAD];
    __nv_bfloat16 Bl[GBN][SPAD];
};

__device__ __forceinline__ void ldsm_x4(uint32_t& r0, uint32_t& r1,
                                        uint32_t& r2, uint32_t& r3, uint32_t addr) {
    asm volatile("ldmatrix.sync.aligned.m8n8.x4.shared.b16 {%0,%1,%2,%3}, [%4];"
                 : "=r"(r0), "=r"(r1), "=r"(r2), "=r"(r3) : "r"(addr));
}

__device__ __forceinline__ void mma_bf16(float* d, const uint32_t* a,
                                         uint32_t b0, uint32_t b1) {
    asm volatile(
        "mma.sync.aligned.m16n8k16.row.col.f32.bf16.bf16.f32 "
        "{%0,%1,%2,%3}, {%4,%5,%6,%7}, {%8,%9}, {%0,%1,%2,%3};"
        : "+f"(d[0]), "+f"(d[1]), "+f"(d[2]), "+f"(d[3])
        : "r"(a[0]), "r"(a[1]), "r"(a[2]), "r"(a[3]), "r"(b0), "r"(b1));
}

__device__ __forceinline__ void split_store(__nv_bfloat16* hi, __nv_bfloat16* lo, float v) {
    __nv_bfloat16 h = __float2bfloat16(v);
    *hi = h;
    *lo = __float2bfloat16(v - __bfloat162float(h));
}

// Load A tile [row0..row0+127, k0..k0+31] (fp32, row stride kstride) with per-row scale.
__device__ __forceinline__ void load_A_tile(GemmSmem* sm, const float* A, int row0,
                                            int k0, int kstride, const float* rs) {
    int t = threadIdx.x;
    int lr = t >> 3;        // 0..31
    int lc = t & 7;         // float4 column
#pragma unroll
    for (int p = 0; p < 4; p++) {
        int r = lr + p * 32;
        int grow = row0 + r;
        float4 v = make_float4(0.f, 0.f, 0.f, 0.f);
        if (grow < N_NODES)
            v = *(const float4*)(A + (long)grow * kstride + k0 + lc * 4);
        float s = rs[p];
        v.x *= s; v.y *= s; v.z *= s; v.w *= s;
        int c = lc * 4;
        split_store(&sm->Ah[r][c + 0], &sm->Al[r][c + 0], v.x);
        split_store(&sm->Ah[r][c + 1], &sm->Al[r][c + 1], v.y);
        split_store(&sm->Ah[r][c + 2], &sm->Al[r][c + 2], v.z);
        split_store(&sm->Ah[r][c + 3], &sm->Al[r][c + 3], v.w);
    }
}

// Load B tile [k0..k0+31, col0..col0+127] (fp32 weights, row stride nstride),
// stored transposed into smem as [n][k].
__device__ __forceinline__ void load_B_tile(GemmSmem* sm, const float* B, int k0,
                                            int col0, int nstride) {
    int t = threadIdx.x;
    int kr = t >> 5;        // 0..7
    int nc = t & 31;        // float4 column over 128 cols
#pragma unroll
    for (int p = 0; p < 4; p++) {
        int k = kr + p * 8;  // 0..31
        float4 v = *(const float4*)(B + (long)(k0 + k) * nstride + col0 + nc * 4);
        int n = nc * 4;
        split_store(&sm->Bh[n + 0][k], &sm->Bl[n + 0][k], v.x);
        split_store(&sm->Bh[n + 1][k], &sm->Bl[n + 1][k], v.y);
        split_store(&sm->Bh[n + 2][k], &sm->Bl[n + 2][k], v.z);
        split_store(&sm->Bh[n + 3][k], &sm->Bl[n + 3][k], v.w);
    }
}

// MMA over one BK=32 chunk. acc[2][8][4].
__device__ __forceinline__ void mma_chunk(GemmSmem* sm, float acc[2][8][4],
                                          int wm, int wn, int lane) {
    uint32_t baseAh = (uint32_t)__cvta_generic_to_shared(&sm->Ah[0][0]);
    uint32_t baseAl = (uint32_t)__cvta_generic_to_shared(&sm->Al[0][0]);
    uint32_t baseBh = (uint32_t)__cvta_generic_to_shared(&sm->Bh[0][0]);
    uint32_t baseBl = (uint32_t)__cvta_generic_to_shared(&sm->Bl[0][0]);
#pragma unroll
    for (int ks = 0; ks < 2; ks++) {
        // A fragments (hi & lo) for 2 m16 tiles
        uint32_t ah[2][4], al[2][4];
#pragma unroll
        for (int mi = 0; mi < 2; mi++) {
            int row = wm * 32 + mi * 16 + (lane & 15);
            int col = ks * 16 + ((lane >> 4) << 3);
            uint32_t off = (uint32_t)(row * SPAD + col) * 2;
            ldsm_x4(ah[mi][0], ah[mi][1], ah[mi][2], ah[mi][3], baseAh + off);
            ldsm_x4(al[mi][0], al[mi][1], al[mi][2], al[mi][3], baseAl + off);
        }
        // B fragments per n16 group, then 12 MMAs
#pragma unroll
        for (int nj = 0; nj < 4; nj++) {
            int row = wn * 64 + nj * 16 + ((lane >> 4) << 3) + (lane & 7);
            int col = ks * 16 + ((lane >> 3) & 1) * 8;
            uint32_t off = (uint32_t)(row * SPAD + col) * 2;
            uint32_t bh0, bh1, bh2, bh3, bl0, bl1, bl2, bl3;
            ldsm_x4(bh0, bh1, bh2, bh3, baseBh + off);
            ldsm_x4(bl0, bl1, bl2, bl3, baseBl + off);
#pragma unroll
            for (int mi = 0; mi < 2; mi++) {
                mma_bf16(acc[mi][nj * 2 + 0], ah[mi], bh0, bh1);
                mma_bf16(acc[mi][nj * 2 + 0], ah[mi], bl0, bl1);
                mma_bf16(acc[mi][nj * 2 + 0], al[mi], bh0, bh1);
                mma_bf16(acc[mi][nj * 2 + 1], ah[mi], bh2, bh3);
                mma_bf16(acc[mi][nj * 2 + 1], ah[mi], bl2, bl3);
                mma_bf16(acc[mi][nj * 2 + 1], al[mi], bh2, bh3);
            }
        }
    }
}

// h = relu(mean1 @ W1_l + x @ W1_r + b1)
__global__ __launch_bounds__(256, 2)
void gemm1_tc(const float* __restrict__ x,
              const float* __restrict__ W1l,
              const float* __restrict__ W1r,
              const float* __restrict__ b1) {
    __shared__ __align__(16) GemmSmem sm;
    float acc[2][8][4];
#pragma unroll
    for (int i = 0; i < 2; i++)
#pragma unroll
        for (int j = 0; j < 8; j++)
#pragma unroll
            for (int k = 0; k < 4; k++) acc[i][j][k] = 0.f;

    int tid  = threadIdx.x;
    int lane = tid & 31;
    int wid  = tid >> 5;
    int wm = wid & 3;       // 4 m-warps
    int wn = wid >> 2;      // 2 n-warps
    int row0 = blockIdx.x * GBM;
    int col0 = blockIdx.y * GBN;

    // per-row scales for pass 0 (mean): rdeg of the 4 rows this thread loads
    int lr = tid >> 3;
    float rs_mean[4], rs_one[4];
#pragma unroll
    for (int p = 0; p < 4; p++) {
        int grow = row0 + lr + p * 32;
        rs_mean[p] = (grow < N_NODES) ? g_rdeg[grow] : 0.f;
        rs_one[p] = 1.f;
    }

#pragma unroll 1
    for (int pass = 0; pass < 2; pass++) {
        const float* A = pass ? x : g_agg1;
        const float* B = pass ? W1r : W1l;
        const float* rs = pass ? rs_one : rs_mean;
#pragma unroll 1
        for (int k0 = 0; k0 < D_IN; k0 += GBK) {
            __syncthreads();
            load_A_tile(&sm, A, row0, k0, D_IN, rs);
            load_B_tile(&sm, B, k0, col0, D_HID);
            __syncthreads();
            mma_chunk(&sm, acc, wm, wn, lane);
        }
    }

    // epilogue: bias + relu -> g_h
    int g = lane >> 2, tg = lane & 3;
#pragma unroll
    for (int mi = 0; mi < 2; mi++) {
        int r = row0 + wm * 32 + mi * 16 + g;
#pragma unroll
        for (int t = 0; t < 8; t++) {
            int c = col0 + wn * 64 + t * 8 + tg * 2;
            float bb0 = b1[c], bb1 = b1[c + 1];
            if (r < N_NODES) {
                float2 o;
                o.x = fmaxf(acc[mi][t][0] + bb0, 0.f);
                o.y = fmaxf(acc[mi][t][1] + bb1, 0.f);
                *(float2*)(g_h + (long)r * D_HID + c) = o;
            }
            if (r + 8 < N_NODES) {
                float2 o;
                o.x = fmaxf(acc[mi][t][2] + bb0, 0.f);
                o.y = fmaxf(acc[mi][t][3] + bb1, 0.f);
                *(float2*)(g_h + (long)(r + 8) * D_HID + c) = o;
            }
        }
    }
}

// blockIdx.y==0: y2 = h @ W2_l ; blockIdx.y==1: z2 = h @ W2_r + b2
__global__ __launch_bounds__(256, 2)
void gemm2_tc(const float* __restrict__ W2l,
              const float* __restrict__ W2r,
              const float* __restrict__ b2) {
    __shared__ __align__(16) GemmSmem sm;
    float acc[2][8][4];
#pragma unroll
    for (int i = 0; i < 2; i++)
#pragma unroll
        for (int j = 0; j < 8; j++)
#pragma unroll
            for (int k = 0; k < 4; k++) acc[i][j][k] = 0.f;

    int tid  = threadIdx.x;
    int lane = tid & 31;
    int wid  = tid >> 5;
    int wm = wid & 3;
    int wn = wid >> 2;
    int row0 = blockIdx.x * GBM;
    bool second = (blockIdx.y == 1);
    const float* B = second ? W2r : W2l;   // [256][128]
    float* C = second ? g_z2 : g_y2;

    float rs_one[4] = {1.f, 1.f, 1.f, 1.f};

#pragma unroll 1
    for (int k0 = 0; k0 < D_HID; k0 += GBK) {
        __syncthreads();
        load_A_tile(&sm, g_h, row0, k0, D_HID, rs_one);
        load_B_tile(&sm, B, k0, 0, D_OUT);
        __syncthreads();
        mma_chunk(&sm, acc, wm, wn, lane);
    }

    int g = lane >> 2, tg = lane & 3;
#pragma unroll
    for (int mi = 0; mi < 2; mi++) {
        int r = row0 + wm * 32 + mi * 16 + g;
#pragma unroll
        for (int t = 0; t < 8; t++) {
            int c = wn * 64 + t * 8 + tg * 2;
            float bb0 = second ? b2[c] : 0.f;
            float bb1 = second ? b2[c + 1] : 0.f;
            if (r < N_NODES) {
                float2 o;
                o.x = acc[mi][t][0] + bb0;
                o.y = acc[mi][t][1] + bb1;
                *(float2*)(C + (long)r * D_OUT + c) = o;
            }
            if (r + 8 < N_NODES) {
                float2 o;
                o.x = acc[mi][t][2] + bb0;
                o.y = acc[mi][t][3] + bb1;
                *(float2*)(C + (long)(r + 8) * D_OUT + c) = o;
            }
        }
    }
}

// out = agg2 * rdeg + z2
__global__ void final_kernel(float* __restrict__ out) {
    long tid    = (long)blockIdx.x * blockDim.x + threadIdx.x;
    long stride = (long)gridDim.x * blockDim.x;
    const long n = (long)N_NODES * D_OUT / 4;
    for (long i = tid; i < n; i += stride) {
        int node = (int)(i >> 5);
        float r = g_rdeg[node];
        float4 a = ((const float4*)g_agg2)[i];
        float4 z = ((const float4*)g_z2)[i];
        float4 o;
        o.x = a.x * r + z.x;
        o.y = a.y * r + z.y;
        o.z = a.z * r + z.z;
        o.w = a.w * r + z.w;
        ((float4*)out)[i] = o;
    }
}

extern "C" void kernel_launch(void* const* d_in, const int* in_sizes, int n_in,
                              void* d_out, int out_size) {
    const float* x   = (const float*)d_in[0];
    const int*   ei  = (const int*)d_in[1];
    const float* W1l = (const float*)d_in[2];
    const float* b1  = (const float*)d_in[3];
    const float* W1r = (const float*)d_in[4];
    const float* W2l = (const float*)d_in[5];
    const float* b2  = (const float*)d_in[6];
    const float* W2r = (const float*)d_in[7];
    float* out = (float*)d_out;

    zero_kernel<<<1184, 256>>>();
    degree_kernel<<<(N_EDGES + 255) / 256, 256>>>(ei);
    rdeg_kernel<<<(N_NODES + 255) / 256, 256>>>();
    scatter1_kernel<<<(int)(((long)N_EDGES * 32 + 255) / 256), 256>>>(x, ei);

    dim3 g1((N_NODES + GBM - 1) / GBM, 2);
    gemm1_tc<<<g1, 256>>>(x, W1l, W1r, b1);
    gemm2_tc<<<g1, 256>>>(W2l, W2r, b2);

    scatter2_kernel<<<(int)(((long)N_EDGES * 32 + 255) / 256), 256>>>(ei);
    final_kernel<<<592, 256>>>(out);
}

// round 5
// speedup vs baseline: 1.8723x; 1.7951x over previous
#include <cuda_runtime.h>
#include <cuda_bf16.h>
#include <cstdint>

#define N_NODES 50000
#define N_EDGES 800000
#define D_IN    256
#define D_HID   256
#define D_OUT   128

// ---- scratch (no allocations allowed) ----
__device__ __nv_bfloat16 g_xh [N_NODES * D_IN];   // split(x)
__device__ __nv_bfloat16 g_xl [N_NODES * D_IN];
__device__ __nv_bfloat16 g_m1h[N_NODES * D_IN];   // split(mean1)
__device__ __nv_bfloat16 g_m1l[N_NODES * D_IN];
__device__ __nv_bfloat16 g_hh [N_NODES * D_HID];  // split(h)
__device__ __nv_bfloat16 g_hl [N_NODES * D_HID];
__device__ __nv_bfloat16 g_w1h[D_HID * 2 * D_IN]; // B1^T: [256 n][512 k]
__device__ __nv_bfloat16 g_w1l[D_HID * 2 * D_IN];
__device__ __nv_bfloat16 g_w2h[2 * D_OUT * D_HID];// B2^T: [256 n][256 k]
__device__ __nv_bfloat16 g_w2l[2 * D_OUT * D_HID];
__device__ float g_y2[N_NODES * D_OUT];           // h @ W2_l
__device__ float g_z2[N_NODES * D_OUT];           // h @ W2_r + b2
__device__ int   g_deg[N_NODES];
__device__ int   g_rowstart[N_NODES + 1];
__device__ int   g_cursor[N_NODES];
__device__ int   g_csr[N_EDGES];

__device__ __forceinline__ int clampi(int v) {
    return min(max(v, 0), N_NODES - 1);
}

__device__ __forceinline__ void split1(float v, __nv_bfloat16& h, __nv_bfloat16& l) {
    h = __float2bfloat16(v);
    l = __float2bfloat16(v - __bfloat162float(h));
}

__device__ __forceinline__ uint32_t bpack(__nv_bfloat16 a, __nv_bfloat16 b) {
    union { __nv_bfloat162 v; uint32_t u; } t;
    t.v.x = a; t.v.y = b;
    return t.u;
}

// ---- per-launch reset (kernel_launch must be idempotent across calls!) ----
__global__ void zero_deg_kernel() {
    int i = blockIdx.x * blockDim.x + threadIdx.x;
    if (i < N_NODES) g_deg[i] = 0;
}

// ---- one-time conversions (pure functions of inputs; safe to redo) ----
__global__ void convert_x_kernel(const float* __restrict__ x) {
    long i = (long)blockIdx.x * blockDim.x + threadIdx.x;
    const long n = (long)N_NODES * D_IN / 4;
    if (i >= n) return;
    float4 v = ((const float4*)x)[i];
    __nv_bfloat16 h0, h1, h2, h3, l0, l1, l2, l3;
    split1(v.x, h0, l0); split1(v.y, h1, l1);
    split1(v.z, h2, l2); split1(v.w, h3, l3);
    ((uint2*)g_xh)[i] = make_uint2(bpack(h0, h1), bpack(h2, h3));
    ((uint2*)g_xl)[i] = make_uint2(bpack(l0, l1), bpack(l2, l3));
}

// transposed + split weight matrices
__global__ void convert_w_kernel(const float* __restrict__ W1l,
                                 const float* __restrict__ W1r,
                                 const float* __restrict__ W2l,
                                 const float* __restrict__ W2r) {
    int i = blockIdx.x * blockDim.x + threadIdx.x;
    const int n1 = D_HID * 2 * D_IN;       // 131072
    const int n2 = 2 * D_OUT * D_HID;      // 65536
    if (i < n1) {
        int n = i >> 9, k = i & 511;
        float v = (k < 256) ? W1l[k * D_HID + n] : W1r[(k - 256) * D_HID + n];
        split1(v, g_w1h[i], g_w1l[i]);
    } else if (i < n1 + n2) {
        int j = i - n1;
        int n = j >> 8, k = j & 255;
        float v = (n < 128) ? W2l[k * D_OUT + n] : W2r[k * D_OUT + (n - 128)];
        split1(v, g_w2h[j], g_w2l[j]);
    }
}

// ---- CSR build ----
__global__ void degree_kernel(const int* __restrict__ ei) {
    int e = blockIdx.x * blockDim.x + threadIdx.x;
    if (e < N_EDGES) atomicAdd(&g_deg[clampi(ei[N_EDGES + e])], 1);
}

__global__ void scan_kernel() {
    __shared__ int part[1024];
    int t = threadIdx.x;
    const int CH = (N_NODES + 1023) / 1024;  // 49
    int lo = t * CH, hi = min(lo + CH, N_NODES);
    int s = 0;
    for (int i = lo; i < hi; i++) s += g_deg[i];
    part[t] = s;
    __syncthreads();
    for (int off = 1; off < 1024; off <<= 1) {
        int v = (t >= off) ? part[t - off] : 0;
        __syncthreads();
        part[t] += v;
        __syncthreads();
    }
    int run = (t == 0) ? 0 : part[t - 1];
    for (int i = lo; i < hi; i++) {
        g_rowstart[i] = run;
        g_cursor[i] = run;
        run += g_deg[i];
    }
    if (t == 1023) g_rowstart[N_NODES] = run;
}

__global__ void fill_kernel(const int* __restrict__ ei) {
    int e = blockIdx.x * blockDim.x + threadIdx.x;
    if (e >= N_EDGES) return;
    int dst = clampi(ei[N_EDGES + e]);
    int slot = atomicAdd(&g_cursor[dst], 1);
    g_csr[slot] = clampi(ei[e]);
}

// ---- gather1: mean of x over in-neighbors -> split bf16 (warp per node) ----
__global__ void gather1_kernel(const float* __restrict__ x) {
    int node = (int)((blockIdx.x * (long)blockDim.x + threadIdx.x) >> 5);
    int lane = threadIdx.x & 31;
    if (node >= N_NODES) return;
    int s = g_rowstart[node], e = g_rowstart[node + 1];
    float acc[8];
#pragma unroll
    for (int j = 0; j < 8; j++) acc[j] = 0.f;
    for (int i = s; i < e; i++) {
        int src = g_csr[i];
        const float4* xr = (const float4*)(x + (long)src * D_IN);
        float4 a = xr[lane * 2], b = xr[lane * 2 + 1];
        acc[0] += a.x; acc[1] += a.y; acc[2] += a.z; acc[3] += a.w;
        acc[4] += b.x; acc[5] += b.y; acc[6] += b.z; acc[7] += b.w;
    }
    float r = 1.0f / fmaxf((float)(e - s), 1.0f);
    __nv_bfloat16 h[8], l[8];
#pragma unroll
    for (int j = 0; j < 8; j++) split1(acc[j] * r, h[j], l[j]);
    uint4 ph = make_uint4(bpack(h[0], h[1]), bpack(h[2], h[3]),
                          bpack(h[4], h[5]), bpack(h[6], h[7]));
    uint4 pl = make_uint4(bpack(l[0], l[1]), bpack(l[2], l[3]),
                          bpack(l[4], l[5]), bpack(l[6], l[7]));
    ((uint4*)(g_m1h + (long)node * D_IN))[lane] = ph;
    ((uint4*)(g_m1l + (long)node * D_IN))[lane] = pl;
}

// ======================================================================
// bf16 split-3-pass tensor GEMM. Block 128x128, BK=32, 256 thr, 8 warps.
// Operands pre-split in gmem; cp.async loads; SPAD=40 conflict-free ldsm.
// ======================================================================
#define GBM 128
#define GBN 128
#define GBK 32
#define SPAD 40

struct GemmSmem {
    __nv_bfloat16 Ah[GBM][SPAD];
    __nv_bfloat16 Al[GBM][SPAD];
    __nv_bfloat16 Bh[GBN][SPAD];
    __nv_bfloat16 Bl[GBN][SPAD];
};

__device__ __forceinline__ void cpa16(uint32_t dst, const void* src, int srcsize) {
    asm volatile("cp.async.ca.shared.global [%0], [%1], 16, %2;"
                 :: "r"(dst), "l"(src), "r"(srcsize));
}

__device__ __forceinline__ void ldsm_x4(uint32_t& r0, uint32_t& r1,
                                        uint32_t& r2, uint32_t& r3, uint32_t addr) {
    asm volatile("ldmatrix.sync.aligned.m8n8.x4.shared.b16 {%0,%1,%2,%3}, [%4];"
                 : "=r"(r0), "=r"(r1), "=r"(r2), "=r"(r3) : "r"(addr));
}

__device__ __forceinline__ void mma_bf16(float* d, const uint32_t* a,
                                         uint32_t b0, uint32_t b1) {
    asm volatile(
        "mma.sync.aligned.m16n8k16.row.col.f32.bf16.bf16.f32 "
        "{%0,%1,%2,%3}, {%4,%5,%6,%7}, {%8,%9}, {%0,%1,%2,%3};"
        : "+f"(d[0]), "+f"(d[1]), "+f"(d[2]), "+f"(d[3])
        : "r"(a[0]), "r"(a[1]), "r"(a[2]), "r"(a[3]), "r"(b0), "r"(b1));
}

// load one chunk: A[row0.., ka..ka+31] (strided asr), B rows coln0.. of Bt (strided bsr)
__device__ __forceinline__ void load_chunk(GemmSmem* sm,
        const __nv_bfloat16* Ah, const __nv_bfloat16* Al, int row0, int ka, int asr,
        const __nv_bfloat16* Bh, const __nv_bfloat16* Bl, int coln0, int kb, int bsr) {
    uint32_t bAh = (uint32_t)__cvta_generic_to_shared(&sm->Ah[0][0]);
    uint32_t bAl = (uint32_t)__cvta_generic_to_shared(&sm->Al[0][0]);
    uint32_t bBh = (uint32_t)__cvta_generic_to_shared(&sm->Bh[0][0]);
    uint32_t bBl = (uint32_t)__cvta_generic_to_shared(&sm->Bl[0][0]);
    int t = threadIdx.x;
#pragma unroll
    for (int p = 0; p < 2; p++) {
        int idx = t + p * 256;
        int row = idx >> 2, seg = idx & 3;
        uint32_t soff = (uint32_t)(row * SPAD + seg * 8) * 2;
        int grow = row0 + row;
        int pred = (grow < N_NODES) ? 16 : 0;
        long aoff = (long)min(grow, N_NODES - 1) * asr + ka + seg * 8;
        cpa16(bAh + soff, Ah + aoff, pred);
        cpa16(bAl + soff, Al + aoff, pred);
        long boff = (long)(coln0 + row) * bsr + kb + seg * 8;
        cpa16(bBh + soff, Bh + boff, 16);
        cpa16(bBl + soff, Bl + boff, 16);
    }
    asm volatile("cp.async.commit_group;");
}

__device__ __forceinline__ void mma_chunk(GemmSmem* sm, float acc[2][8][4],
                                          int wm, int wn, int lane) {
    uint32_t baseAh = (uint32_t)__cvta_generic_to_shared(&sm->Ah[0][0]);
    uint32_t baseAl = (uint32_t)__cvta_generic_to_shared(&sm->Al[0][0]);
    uint32_t baseBh = (uint32_t)__cvta_generic_to_shared(&sm->Bh[0][0]);
    uint32_t baseBl = (uint32_t)__cvta_generic_to_shared(&sm->Bl[0][0]);
#pragma unroll
    for (int ks = 0; ks < 2; ks++) {
        uint32_t ah[2][4], al[2][4];
#pragma unroll
        for (int mi = 0; mi < 2; mi++) {
            int row = wm * 32 + mi * 16 + (lane & 15);
            int col = ks * 16 + ((lane >> 4) << 3);
            uint32_t off = (uint32_t)(row * SPAD + col) * 2;
            ldsm_x4(ah[mi][0], ah[mi][1], ah[mi][2], ah[mi][3], baseAh + off);
            ldsm_x4(al[mi][0], al[mi][1], al[mi][2], al[mi][3], baseAl + off);
        }
#pragma unroll
        for (int nj = 0; nj < 4; nj++) {
            int row = wn * 64 + nj * 16 + ((lane >> 4) << 3) + (lane & 7);
            int col = ks * 16 + ((lane >> 3) & 1) * 8;
            uint32_t off = (uint32_t)(row * SPAD + col) * 2;
            uint32_t bh0, bh1, bh2, bh3, bl0, bl1, bl2, bl3;
            ldsm_x4(bh0, bh1, bh2, bh3, baseBh + off);
            ldsm_x4(bl0, bl1, bl2, bl3, baseBl + off);
#pragma unroll
            for (int mi = 0; mi < 2; mi++) {
                mma_bf16(acc[mi][nj * 2 + 0], ah[mi], bh0, bh1);
                mma_bf16(acc[mi][nj * 2 + 0], ah[mi], bl0, bl1);
                mma_bf16(acc[mi][nj * 2 + 0], al[mi], bh0, bh1);
                mma_bf16(acc[mi][nj * 2 + 1], ah[mi], bh2, bh3);
                mma_bf16(acc[mi][nj * 2 + 1], ah[mi], bl2, bl3);
                mma_bf16(acc[mi][nj * 2 + 1], al[mi], bh2, bh3);
            }
        }
    }
}

// h = relu([mean1|x] @ [W1l;W1r] + b1) -> split bf16
__global__ __launch_bounds__(256, 2)
void gemm1_tc(const float* __restrict__ b1) {
    __shared__ __align__(16) GemmSmem sm;
    float acc[2][8][4];
#pragma unroll
    for (int i = 0; i < 2; i++)
#pragma unroll
        for (int j = 0; j < 8; j++)
#pragma unroll
            for (int k = 0; k < 4; k++) acc[i][j][k] = 0.f;

    int lane = threadIdx.x & 31;
    int wid  = threadIdx.x >> 5;
    int wm = wid & 3, wn = wid >> 2;
    int row0 = blockIdx.x * GBM;
    int col0 = blockIdx.y * GBN;

#pragma unroll 1
    for (int c = 0; c < 16; c++) {
        int k0 = c * GBK;
        const __nv_bfloat16 *Asrc_h, *Asrc_l;
        int kk;
        if (k0 < 256) { Asrc_h = g_m1h; Asrc_l = g_m1l; kk = k0; }
        else          { Asrc_h = g_xh;  Asrc_l = g_xl;  kk = k0 - 256; }
        __syncthreads();
        load_chunk(&sm, Asrc_h, Asrc_l, row0, kk, D_IN,
                   g_w1h, g_w1l, col0, k0, 2 * D_IN);
        asm volatile("cp.async.wait_group 0;");
        __syncthreads();
        mma_chunk(&sm, acc, wm, wn, lane);
    }

    int g = lane >> 2, tg = lane & 3;
#pragma unroll
    for (int mi = 0; mi < 2; mi++) {
        int r = row0 + wm * 32 + mi * 16 + g;
#pragma unroll
        for (int t = 0; t < 8; t++) {
            int c = col0 + wn * 64 + t * 8 + tg * 2;
            float bb0 = b1[c], bb1 = b1[c + 1];
            if (r < N_NODES) {
                float v0 = fmaxf(acc[mi][t][0] + bb0, 0.f);
                float v1 = fmaxf(acc[mi][t][1] + bb1, 0.f);
                __nv_bfloat16 h0, h1, l0, l1;
                split1(v0, h0, l0); split1(v1, h1, l1);
                *(uint32_t*)(g_hh + (long)r * D_HID + c) = bpack(h0, h1);
                *(uint32_t*)(g_hl + (long)r * D_HID + c) = bpack(l0, l1);
            }
            if (r + 8 < N_NODES) {
                float v0 = fmaxf(acc[mi][t][2] + bb0, 0.f);
                float v1 = fmaxf(acc[mi][t][3] + bb1, 0.f);
                __nv_bfloat16 h0, h1, l0, l1;
                split1(v0, h0, l0); split1(v1, h1, l1);
                *(uint32_t*)(g_hh + (long)(r + 8) * D_HID + c) = bpack(h0, h1);
                *(uint32_t*)(g_hl + (long)(r + 8) * D_HID + c) = bpack(l0, l1);
            }
        }
    }
}

// [y2|z2] = h @ [W2l|W2r] (+b2 on z2 half)
__global__ __launch_bounds__(256, 2)
void gemm2_tc(const float* __restrict__ b2) {
    __shared__ __align__(16) GemmSmem sm;
    float acc[2][8][4];
#pragma unroll
    for (int i = 0; i < 2; i++)
#pragma unroll
        for (int j = 0; j < 8; j++)
#pragma unroll
            for (int k = 0; k < 4; k++) acc[i][j][k] = 0.f;

    int lane = threadIdx.x & 31;
    int wid  = threadIdx.x >> 5;
    int wm = wid & 3, wn = wid >> 2;
    int row0 = blockIdx.x * GBM;
    int col0 = blockIdx.y * GBN;

#pragma unroll 1
    for (int c = 0; c < 8; c++) {
        int k0 = c * GBK;
        __syncthreads();
        load_chunk(&sm, g_hh, g_hl, row0, k0, D_HID,
                   g_w2h, g_w2l, col0, k0, D_HID);
        asm volatile("cp.async.wait_group 0;");
        __syncthreads();
        mma_chunk(&sm, acc, wm, wn, lane);
    }

    int g = lane >> 2, tg = lane & 3;
#pragma unroll
    for (int mi = 0; mi < 2; mi++) {
        int r = row0 + wm * 32 + mi * 16 + g;
#pragma unroll
        for (int t = 0; t < 8; t++) {
            int cg = col0 + wn * 64 + t * 8 + tg * 2;   // 0..255
            bool zside = (cg >= 128);
            int cl = zside ? cg - 128 : cg;
            float bb0 = zside ? b2[cl] : 0.f;
            float bb1 = zside ? b2[cl + 1] : 0.f;
            float* C = zside ? g_z2 : g_y2;
            if (r < N_NODES) {
                float2 o = make_float2(acc[mi][t][0] + bb0, acc[mi][t][1] + bb1);
                *(float2*)(C + (long)r * D_OUT + cl) = o;
            }
            if (r + 8 < N_NODES) {
                float2 o = make_float2(acc[mi][t][2] + bb0, acc[mi][t][3] + bb1);
                *(float2*)(C + (long)(r + 8) * D_OUT + cl) = o;
            }
        }
    }
}

// ---- gather2 + final: out = mean(y2 over in-neighbors) + z2  (warp per node) ----
__global__ void gather2_final_kernel(float* __restrict__ out) {
    int node = (int)((blockIdx.x * (long)blockDim.x + threadIdx.x) >> 5);
    int lane = threadIdx.x & 31;
    if (node >= N_NODES) return;
    int s = g_rowstart[node], e = g_rowstart[node + 1];
    float a0 = 0.f, a1 = 0.f, a2 = 0.f, a3 = 0.f;
    for (int i = s; i < e; i++) {
        int src = g_csr[i];
        float4 v = ((const float4*)(g_y2 + (long)src * D_OUT))[lane];
        a0 += v.x; a1 += v.y; a2 += v.z; a3 += v.w;
    }
    float r = 1.0f / fmaxf((float)(e - s), 1.0f);
    float4 z = ((const float4*)(g_z2 + (long)node * D_OUT))[lane];
    float4 o;
    o.x = a0 * r + z.x;
    o.y = a1 * r + z.y;
    o.z = a2 * r + z.z;
    o.w = a3 * r + z.w;
    ((float4*)(out + (long)node * D_OUT))[lane] = o;
}

extern "C" void kernel_launch(void* const* d_in, const int* in_sizes, int n_in,
                              void* d_out, int out_size) {
    const float* x   = (const float*)d_in[0];
    const int*   ei  = (const int*)d_in[1];
    const float* W1l = (const float*)d_in[2];
    const float* b1  = (const float*)d_in[3];
    const float* W1r = (const float*)d_in[4];
    const float* W2l = (const float*)d_in[5];
    const float* b2  = (const float*)d_in[6];
    const float* W2r = (const float*)d_in[7];
    float* out = (float*)d_out;

    zero_deg_kernel<<<(N_NODES + 255) / 256, 256>>>();
    convert_x_kernel<<<(N_NODES * D_IN / 4 + 255) / 256, 256>>>(x);
    convert_w_kernel<<<768, 256>>>(W1l, W1r, W2l, W2r);
    degree_kernel<<<(N_EDGES + 255) / 256, 256>>>(ei);
    scan_kernel<<<1, 1024>>>();
    fill_kernel<<<(N_EDGES + 255) / 256, 256>>>(ei);
    gather1_kernel<<<(N_NODES * 32 + 255) / 256, 256>>>(x);

    gemm1_tc<<<dim3((N_NODES + GBM - 1) / GBM, 2), 256>>>(b1);
    gemm2_tc<<<dim3((N_NODES + GBM - 1) / GBM, 2), 256>>>(b2);

    gather2_final_kernel<<<(N_NODES * 32 + 255) / 256, 256>>>(out);
}

// round 6
// speedup vs baseline: 1.8890x; 1.0089x over previous
#include <cuda_runtime.h>
#include <cuda_bf16.h>
#include <cstdint>

#define N_NODES 50000
#define N_EDGES 800000
#define D_IN    256
#define D_HID   256
#define D_OUT   128

// ---- scratch (no allocations allowed) ----
__device__ __nv_bfloat16 g_xh [N_NODES * D_IN];   // split(x)
__device__ __nv_bfloat16 g_xl [N_NODES * D_IN];
__device__ __nv_bfloat16 g_m1h[N_NODES * D_IN];   // split(mean1)
__device__ __nv_bfloat16 g_m1l[N_NODES * D_IN];
__device__ __nv_bfloat16 g_hh [N_NODES * D_HID];  // split(h)
__device__ __nv_bfloat16 g_hl [N_NODES * D_HID];
__device__ __nv_bfloat16 g_w1h[D_HID * 2 * D_IN]; // B1^T: [256 n][512 k]
__device__ __nv_bfloat16 g_w1l[D_HID * 2 * D_IN];
__device__ __nv_bfloat16 g_w2h[2 * D_OUT * D_HID];// B2^T: [256 n][256 k]
__device__ __nv_bfloat16 g_w2l[2 * D_OUT * D_HID];
__device__ float g_y2[N_NODES * D_OUT];           // h @ W2_l
__device__ float g_z2[N_NODES * D_OUT];           // h @ W2_r + b2
__device__ int   g_deg[N_NODES];
__device__ int   g_rowstart[N_NODES + 1];
__device__ int   g_cursor[N_NODES];
__device__ int   g_csr[N_EDGES];

__device__ __forceinline__ int clampi(int v) {
    return min(max(v, 0), N_NODES - 1);
}

__device__ __forceinline__ void split1(float v, __nv_bfloat16& h, __nv_bfloat16& l) {
    h = __float2bfloat16(v);
    l = __float2bfloat16(v - __bfloat162float(h));
}

__device__ __forceinline__ uint32_t bpack(__nv_bfloat16 a, __nv_bfloat16 b) {
    union { __nv_bfloat162 v; uint32_t u; } t;
    t.v.x = a; t.v.y = b;
    return t.u;
}

// ---- per-launch reset (kernel_launch must be idempotent across calls!) ----
__global__ void zero_deg_kernel() {
    int i = blockIdx.x * blockDim.x + threadIdx.x;
    if (i < N_NODES) g_deg[i] = 0;
}

// ---- one-time conversions (pure functions of inputs; safe to redo) ----
__global__ void convert_x_kernel(const float* __restrict__ x) {
    long i = (long)blockIdx.x * blockDim.x + threadIdx.x;
    const long n = (long)N_NODES * D_IN / 4;
    if (i >= n) return;
    float4 v = ((const float4*)x)[i];
    __nv_bfloat16 h0, h1, h2, h3, l0, l1, l2, l3;
    split1(v.x, h0, l0); split1(v.y, h1, l1);
    split1(v.z, h2, l2); split1(v.w, h3, l3);
    ((uint2*)g_xh)[i] = make_uint2(bpack(h0, h1), bpack(h2, h3));
    ((uint2*)g_xl)[i] = make_uint2(bpack(l0, l1), bpack(l2, l3));
}

// transposed + split weight matrices
__global__ void convert_w_kernel(const float* __restrict__ W1l,
                                 const float* __restrict__ W1r,
                                 const float* __restrict__ W2l,
                                 const float* __restrict__ W2r) {
    int i = blockIdx.x * blockDim.x + threadIdx.x;
    const int n1 = D_HID * 2 * D_IN;       // 131072
    const int n2 = 2 * D_OUT * D_HID;      // 65536
    if (i < n1) {
        int n = i >> 9, k = i & 511;
        float v = (k < 256) ? W1l[k * D_HID + n] : W1r[(k - 256) * D_HID + n];
        split1(v, g_w1h[i], g_w1l[i]);
    } else if (i < n1 + n2) {
        int j = i - n1;
        int n = j >> 8, k = j & 255;
        float v = (n < 128) ? W2l[k * D_OUT + n] : W2r[k * D_OUT + (n - 128)];
        split1(v, g_w2h[j], g_w2l[j]);
    }
}

// ---- CSR build ----
__global__ void degree_kernel(const int* __restrict__ ei) {
    int e = blockIdx.x * blockDim.x + threadIdx.x;
    if (e < N_EDGES) atomicAdd(&g_deg[clampi(ei[N_EDGES + e])], 1);
}

__global__ void scan_kernel() {
    __shared__ int part[1024];
    int t = threadIdx.x;
    const int CH = (N_NODES + 1023) / 1024;  // 49
    int lo = t * CH, hi = min(lo + CH, N_NODES);
    int s = 0;
    for (int i = lo; i < hi; i++) s += g_deg[i];
    part[t] = s;
    __syncthreads();
    for (int off = 1; off < 1024; off <<= 1) {
        int v = (t >= off) ? part[t - off] : 0;
        __syncthreads();
        part[t] += v;
        __syncthreads();
    }
    int run = (t == 0) ? 0 : part[t - 1];
    for (int i = lo; i < hi; i++) {
        g_rowstart[i] = run;
        g_cursor[i] = run;
        run += g_deg[i];
    }
    if (t == 1023) g_rowstart[N_NODES] = run;
}

__global__ void fill_kernel(const int* __restrict__ ei) {
    int e = blockIdx.x * blockDim.x + threadIdx.x;
    if (e >= N_EDGES) return;
    int dst = clampi(ei[N_EDGES + e]);
    int slot = atomicAdd(&g_cursor[dst], 1);
    g_csr[slot] = clampi(ei[e]);
}

// ---- gather1: mean of x over in-neighbors -> split bf16 (warp per node) ----
__global__ void gather1_kernel(const float* __restrict__ x) {
    int node = (int)((blockIdx.x * (long)blockDim.x + threadIdx.x) >> 5);
    int lane = threadIdx.x & 31;
    if (node >= N_NODES) return;
    int s = g_rowstart[node], e = g_rowstart[node + 1];
    float acc[8];
#pragma unroll
    for (int j = 0; j < 8; j++) acc[j] = 0.f;
    for (int i = s; i < e; i++) {
        int src = g_csr[i];
        const float4* xr = (const float4*)(x + (long)src * D_IN);
        float4 a = xr[lane * 2], b = xr[lane * 2 + 1];
        acc[0] += a.x; acc[1] += a.y; acc[2] += a.z; acc[3] += a.w;
        acc[4] += b.x; acc[5] += b.y; acc[6] += b.z; acc[7] += b.w;
    }
    float r = 1.0f / fmaxf((float)(e - s), 1.0f);
    __nv_bfloat16 h[8], l[8];
#pragma unroll
    for (int j = 0; j < 8; j++) split1(acc[j] * r, h[j], l[j]);
    uint4 ph = make_uint4(bpack(h[0], h[1]), bpack(h[2], h[3]),
                          bpack(h[4], h[5]), bpack(h[6], h[7]));
    uint4 pl = make_uint4(bpack(l[0], l[1]), bpack(l[2], l[3]),
                          bpack(l[4], l[5]), bpack(l[6], l[7]));
    ((uint4*)(g_m1h + (long)node * D_IN))[lane] = ph;
    ((uint4*)(g_m1l + (long)node * D_IN))[lane] = pl;
}

// ======================================================================
// bf16 split-3-pass tensor GEMM. Block 128x128, BK=32, 256 thr, 8 warps.
// 2-stage cp.async double buffer (dynamic smem, 2x40KB).
// ======================================================================
#define GBM 128
#define GBN 128
#define GBK 32
#define SPAD 40

struct GemmSmem {
    __nv_bfloat16 Ah[GBM][SPAD];
    __nv_bfloat16 Al[GBM][SPAD];
    __nv_bfloat16 Bh[GBN][SPAD];
    __nv_bfloat16 Bl[GBN][SPAD];
};
#define GEMM_SMEM_BYTES (2 * sizeof(GemmSmem))

__device__ __forceinline__ void cpa16(uint32_t dst, const void* src, int srcsize) {
    asm volatile("cp.async.cg.shared.global [%0], [%1], 16, %2;"
                 :: "r"(dst), "l"(src), "r"(srcsize));
}

__device__ __forceinline__ void ldsm_x4(uint32_t& r0, uint32_t& r1,
                                        uint32_t& r2, uint32_t& r3, uint32_t addr) {
    asm volatile("ldmatrix.sync.aligned.m8n8.x4.shared.b16 {%0,%1,%2,%3}, [%4];"
                 : "=r"(r0), "=r"(r1), "=r"(r2), "=r"(r3) : "r"(addr));
}

__device__ __forceinline__ void mma_bf16(float* d, const uint32_t* a,
                                         uint32_t b0, uint32_t b1) {
    asm volatile(
        "mma.sync.aligned.m16n8k16.row.col.f32.bf16.bf16.f32 "
        "{%0,%1,%2,%3}, {%4,%5,%6,%7}, {%8,%9}, {%0,%1,%2,%3};"
        : "+f"(d[0]), "+f"(d[1]), "+f"(d[2]), "+f"(d[3])
        : "r"(a[0]), "r"(a[1]), "r"(a[2]), "r"(a[3]), "r"(b0), "r"(b1));
}

// load one chunk: A[row0.., ka..ka+31] (strided asr), B rows coln0.. of Bt (strided bsr)
__device__ __forceinline__ void load_chunk(GemmSmem* sm,
        const __nv_bfloat16* Ah, const __nv_bfloat16* Al, int row0, int ka, int asr,
        const __nv_bfloat16* Bh, const __nv_bfloat16* Bl, int coln0, int kb, int bsr) {
    uint32_t bAh = (uint32_t)__cvta_generic_to_shared(&sm->Ah[0][0]);
    uint32_t bAl = (uint32_t)__cvta_generic_to_shared(&sm->Al[0][0]);
    uint32_t bBh = (uint32_t)__cvta_generic_to_shared(&sm->Bh[0][0]);
    uint32_t bBl = (uint32_t)__cvta_generic_to_shared(&sm->Bl[0][0]);
    int t = threadIdx.x;
#pragma unroll
    for (int p = 0; p < 2; p++) {
        int idx = t + p * 256;
        int row = idx >> 2, seg = idx & 3;
        uint32_t soff = (uint32_t)(row * SPAD + seg * 8) * 2;
        int grow = row0 + row;
        int pred = (grow < N_NODES) ? 16 : 0;
        long aoff = (long)min(grow, N_NODES - 1) * asr + ka + seg * 8;
        cpa16(bAh + soff, Ah + aoff, pred);
        cpa16(bAl + soff, Al + aoff, pred);
        long boff = (long)(coln0 + row) * bsr + kb + seg * 8;
        cpa16(bBh + soff, Bh + boff, 16);
        cpa16(bBl + soff, Bl + boff, 16);
    }
    asm volatile("cp.async.commit_group;");
}

__device__ __forceinline__ void mma_chunk(GemmSmem* sm, float acc[2][8][4],
                                          int wm, int wn, int lane) {
    uint32_t baseAh = (uint32_t)__cvta_generic_to_shared(&sm->Ah[0][0]);
    uint32_t baseAl = (uint32_t)__cvta_generic_to_shared(&sm->Al[0][0]);
    uint32_t baseBh = (uint32_t)__cvta_generic_to_shared(&sm->Bh[0][0]);
    uint32_t baseBl = (uint32_t)__cvta_generic_to_shared(&sm->Bl[0][0]);
#pragma unroll
    for (int ks = 0; ks < 2; ks++) {
        uint32_t ah[2][4], al[2][4];
#pragma unroll
        for (int mi = 0; mi < 2; mi++) {
            int row = wm * 32 + mi * 16 + (lane & 15);
            int col = ks * 16 + ((lane >> 4) << 3);
            uint32_t off = (uint32_t)(row * SPAD + col) * 2;
            ldsm_x4(ah[mi][0], ah[mi][1], ah[mi][2], ah[mi][3], baseAh + off);
            ldsm_x4(al[mi][0], al[mi][1], al[mi][2], al[mi][3], baseAl + off);
        }
#pragma unroll
        for (int nj = 0; nj < 4; nj++) {
            int row = wn * 64 + nj * 16 + ((lane >> 4) << 3) + (lane & 7);
            int col = ks * 16 + ((lane >> 3) & 1) * 8;
            uint32_t off = (uint32_t)(row * SPAD + col) * 2;
            uint32_t bh0, bh1, bh2, bh3, bl0, bl1, bl2, bl3;
            ldsm_x4(bh0, bh1, bh2, bh3, baseBh + off);
            ldsm_x4(bl0, bl1, bl2, bl3, baseBl + off);
#pragma unroll
            for (int mi = 0; mi < 2; mi++) {
                mma_bf16(acc[mi][nj * 2 + 0], ah[mi], bh0, bh1);
                mma_bf16(acc[mi][nj * 2 + 0], ah[mi], bl0, bl1);
                mma_bf16(acc[mi][nj * 2 + 0], al[mi], bh0, bh1);
                mma_bf16(acc[mi][nj * 2 + 1], ah[mi], bh2, bh3);
                mma_bf16(acc[mi][nj * 2 + 1], ah[mi], bl2, bl3);
                mma_bf16(acc[mi][nj * 2 + 1], al[mi], bh2, bh3);
            }
        }
    }
}

// h = relu([mean1|x] @ [W1l;W1r] + b1) -> split bf16
__global__ __launch_bounds__(256, 2)
void gemm1_tc(const float* __restrict__ b1) {
    extern __shared__ __align__(16) char smraw[];
    GemmSmem* st = (GemmSmem*)smraw;
    float acc[2][8][4];
#pragma unroll
    for (int i = 0; i < 2; i++)
#pragma unroll
        for (int j = 0; j < 8; j++)
#pragma unroll
            for (int k = 0; k < 4; k++) acc[i][j][k] = 0.f;

    int lane = threadIdx.x & 31;
    int wid  = threadIdx.x >> 5;
    int wm = wid & 3, wn = wid >> 2;
    int row0 = blockIdx.x * GBM;
    int col0 = blockIdx.y * GBN;
    const int NC = 16;

    auto issue = [&](int c) {
        int k0 = c * GBK;
        const __nv_bfloat16 *Asrc_h, *Asrc_l;
        int kk;
        if (k0 < 256) { Asrc_h = g_m1h; Asrc_l = g_m1l; kk = k0; }
        else          { Asrc_h = g_xh;  Asrc_l = g_xl;  kk = k0 - 256; }
        load_chunk(&st[c & 1], Asrc_h, Asrc_l, row0, kk, D_IN,
                   g_w1h, g_w1l, col0, k0, 2 * D_IN);
    };

    issue(0);
#pragma unroll 1
    for (int c = 0; c < NC; c++) {
        if (c + 1 < NC) {
            issue(c + 1);
            asm volatile("cp.async.wait_group 1;");
        } else {
            asm volatile("cp.async.wait_group 0;");
        }
        __syncthreads();
        mma_chunk(&st[c & 1], acc, wm, wn, lane);
        __syncthreads();
    }

    int g = lane >> 2, tg = lane & 3;
#pragma unroll
    for (int mi = 0; mi < 2; mi++) {
        int r = row0 + wm * 32 + mi * 16 + g;
#pragma unroll
        for (int t = 0; t < 8; t++) {
            int c = col0 + wn * 64 + t * 8 + tg * 2;
            float bb0 = b1[c], bb1 = b1[c + 1];
            if (r < N_NODES) {
                float v0 = fmaxf(acc[mi][t][0] + bb0, 0.f);
                float v1 = fmaxf(acc[mi][t][1] + bb1, 0.f);
                __nv_bfloat16 h0, h1, l0, l1;
                split1(v0, h0, l0); split1(v1, h1, l1);
                *(uint32_t*)(g_hh + (long)r * D_HID + c) = bpack(h0, h1);
                *(uint32_t*)(g_hl + (long)r * D_HID + c) = bpack(l0, l1);
            }
            if (r + 8 < N_NODES) {
                float v0 = fmaxf(acc[mi][t][2] + bb0, 0.f);
                float v1 = fmaxf(acc[mi][t][3] + bb1, 0.f);
                __nv_bfloat16 h0, h1, l0, l1;
                split1(v0, h0, l0); split1(v1, h1, l1);
                *(uint32_t*)(g_hh + (long)(r + 8) * D_HID + c) = bpack(h0, h1);
                *(uint32_t*)(g_hl + (long)(r + 8) * D_HID + c) = bpack(l0, l1);
            }
        }
    }
}

// [y2|z2] = h @ [W2l|W2r] (+b2 on z2 half)
__global__ __launch_bounds__(256, 2)
void gemm2_tc(const float* __restrict__ b2) {
    extern __shared__ __align__(16) char smraw[];
    GemmSmem* st = (GemmSmem*)smraw;
    float acc[2][8][4];
#pragma unroll
    for (int i = 0; i < 2; i++)
#pragma unroll
        for (int j = 0; j < 8; j++)
#pragma unroll
            for (int k = 0; k < 4; k++) acc[i][j][k] = 0.f;

    int lane = threadIdx.x & 31;
    int wid  = threadIdx.x >> 5;
    int wm = wid & 3, wn = wid >> 2;
    int row0 = blockIdx.x * GBM;
    int col0 = blockIdx.y * GBN;
    const int NC = 8;

    auto issue = [&](int c) {
        int k0 = c * GBK;
        load_chunk(&st[c & 1], g_hh, g_hl, row0, k0, D_HID,
                   g_w2h, g_w2l, col0, k0, D_HID);
    };

    issue(0);
#pragma unroll 1
    for (int c = 0; c < NC; c++) {
        if (c + 1 < NC) {
            issue(c + 1);
            asm volatile("cp.async.wait_group 1;");
        } else {
            asm volatile("cp.async.wait_group 0;");
        }
        __syncthreads();
        mma_chunk(&st[c & 1], acc, wm, wn, lane);
        __syncthreads();
    }

    int g = lane >> 2, tg = lane & 3;
#pragma unroll
    for (int mi = 0; mi < 2; mi++) {
        int r = row0 + wm * 32 + mi * 16 + g;
#pragma unroll
        for (int t = 0; t < 8; t++) {
            int cg = col0 + wn * 64 + t * 8 + tg * 2;   // 0..255
            bool zside = (cg >= 128);
            int cl = zside ? cg - 128 : cg;
            float bb0 = zside ? b2[cl] : 0.f;
            float bb1 = zside ? b2[cl + 1] : 0.f;
            float* C = zside ? g_z2 : g_y2;
            if (r < N_NODES) {
                float2 o = make_float2(acc[mi][t][0] + bb0, acc[mi][t][1] + bb1);
                *(float2*)(C + (long)r * D_OUT + cl) = o;
            }
            if (r + 8 < N_NODES) {
                float2 o = make_float2(acc[mi][t][2] + bb0, acc[mi][t][3] + bb1);
                *(float2*)(C + (long)(r + 8) * D_OUT + cl) = o;
            }
        }
    }
}

// ---- gather2 + final: out = mean(y2 over in-neighbors) + z2  (warp per node) ----
__global__ void gather2_final_kernel(float* __restrict__ out) {
    int node = (int)((blockIdx.x * (long)blockDim.x + threadIdx.x) >> 5);
    int lane = threadIdx.x & 31;
    if (node >= N_NODES) return;
    int s = g_rowstart[node], e = g_rowstart[node + 1];
    float a0 = 0.f, a1 = 0.f, a2 = 0.f, a3 = 0.f;
    for (int i = s; i < e; i++) {
        int src = g_csr[i];
        float4 v = ((const float4*)(g_y2 + (long)src * D_OUT))[lane];
        a0 += v.x; a1 += v.y; a2 += v.z; a3 += v.w;
    }
    float r = 1.0f / fmaxf((float)(e - s), 1.0f);
    float4 z = ((const float4*)(g_z2 + (long)node * D_OUT))[lane];
    float4 o;
    o.x = a0 * r + z.x;
    o.y = a1 * r + z.y;
    o.z = a2 * r + z.z;
    o.w = a3 * r + z.w;
    ((float4*)(out + (long)node * D_OUT))[lane] = o;
}

extern "C" void kernel_launch(void* const* d_in, const int* in_sizes, int n_in,
                              void* d_out, int out_size) {
    const float* x   = (const float*)d_in[0];
    const int*   ei  = (const int*)d_in[1];
    const float* W1l = (const float*)d_in[2];
    const float* b1  = (const float*)d_in[3];
    const float* W1r = (const float*)d_in[4];
    const float* W2l = (const float*)d_in[5];
    const float* b2  = (const float*)d_in[6];
    const float* W2r = (const float*)d_in[7];
    float* out = (float*)d_out;

    cudaFuncSetAttribute(gemm1_tc, cudaFuncAttributeMaxDynamicSharedMemorySize,
                         (int)GEMM_SMEM_BYTES);
    cudaFuncSetAttribute(gemm2_tc, cudaFuncAttributeMaxDynamicSharedMemorySize,
                         (int)GEMM_SMEM_BYTES);

    zero_deg_kernel<<<(N_NODES + 255) / 256, 256>>>();
    convert_x_kernel<<<(N_NODES * D_IN / 4 + 255) / 256, 256>>>(x);
    convert_w_kernel<<<768, 256>>>(W1l, W1r, W2l, W2r);
    degree_kernel<<<(N_EDGES + 255) / 256, 256>>>(ei);
    scan_kernel<<<1, 1024>>>();
    fill_kernel<<<(N_EDGES + 255) / 256, 256>>>(ei);
    gather1_kernel<<<(N_NODES * 32 + 255) / 256, 256>>>(x);

    gemm1_tc<<<dim3((N_NODES + GBM - 1) / GBM, 2), 256, GEMM_SMEM_BYTES>>>(b1);
    gemm2_tc<<<dim3((N_NODES + GBM - 1) / GBM, 2), 256, GEMM_SMEM_BYTES>>>(b2);

    gather2_final_kernel<<<(N_NODES * 32 + 255) / 256, 256>>>(out);
}

// round 8
// speedup vs baseline: 2.6098x; 1.3816x over previous
#include <cuda_runtime.h>
#include <cuda_fp16.h>
#include <cstdint>

#define N_NODES 50000
#define N_EDGES 800000
#define D_IN    256
#define D_HID   256
#define D_OUT   128

// ---- scratch (no allocations allowed) ----
__device__ __half g_xf [N_NODES * D_IN];    // fp16(x)
__device__ __half g_m1 [N_NODES * D_IN];    // fp16(mean1)
__device__ __half g_hf [N_NODES * D_HID];   // fp16(h)
__device__ __half g_w1 [D_HID * 2 * D_IN];  // B1^T: [256 n][512 k]
__device__ __half g_w2 [2 * D_OUT * D_HID]; // B2^T: [256 n][256 k]
__device__ float g_y2[N_NODES * D_OUT];     // h @ W2_l
__device__ float g_z2[N_NODES * D_OUT];     // h @ W2_r + b2
__device__ int   g_deg[N_NODES];
__device__ int   g_rowstart[N_NODES + 1];
__device__ int   g_cursor[N_NODES];
__device__ int   g_csr[N_EDGES];

__device__ __forceinline__ int clampi(int v) {
    return min(max(v, 0), N_NODES - 1);
}

__device__ __forceinline__ uint32_t hpack(__half a, __half b) {
    union { __half2 v; uint32_t u; } t;
    t.v.x = a; t.v.y = b;
    return t.u;
}

// ---- per-launch reset (kernel_launch must be idempotent across calls!) ----
__global__ void zero_deg_kernel() {
    int i = blockIdx.x * blockDim.x + threadIdx.x;
    if (i < N_NODES) g_deg[i] = 0;
}

// ---- one-time conversions (pure functions of inputs) ----
__global__ void convert_x_kernel(const float* __restrict__ x) {
    long i = (long)blockIdx.x * blockDim.x + threadIdx.x;
    const long n = (long)N_NODES * D_IN / 4;
    if (i >= n) return;
    float4 v = ((const float4*)x)[i];
    ((uint2*)g_xf)[i] = make_uint2(hpack(__float2half(v.x), __float2half(v.y)),
                                   hpack(__float2half(v.z), __float2half(v.w)));
}

// transposed fp16 weight matrices
__global__ void convert_w_kernel(const float* __restrict__ W1l,
                                 const float* __restrict__ W1r,
                                 const float* __restrict__ W2l,
                                 const float* __restrict__ W2r) {
    int i = blockIdx.x * blockDim.x + threadIdx.x;
    const int n1 = D_HID * 2 * D_IN;       // 131072
    const int n2 = 2 * D_OUT * D_HID;      // 65536
    if (i < n1) {
        int n = i >> 9, k = i & 511;
        float v = (k < 256) ? W1l[k * D_HID + n] : W1r[(k - 256) * D_HID + n];
        g_w1[i] = __float2half(v);
    } else if (i < n1 + n2) {
        int j = i - n1;
        int n = j >> 8, k = j & 255;
        float v = (n < 128) ? W2l[k * D_OUT + n] : W2r[k * D_OUT + (n - 128)];
        g_w2[j] = __float2half(v);
    }
}

// ---- CSR build ----
__global__ void degree_kernel(const int* __restrict__ ei) {
    int e = blockIdx.x * blockDim.x + threadIdx.x;
    if (e < N_EDGES) atomicAdd(&g_deg[clampi(ei[N_EDGES + e])], 1);
}

__global__ void scan_kernel() {
    __shared__ int part[1024];
    int t = threadIdx.x;
    const int CH = (N_NODES + 1023) / 1024;  // 49
    int lo = t * CH, hi = min(lo + CH, N_NODES);
    int s = 0;
    for (int i = lo; i < hi; i++) s += g_deg[i];
    part[t] = s;
    __syncthreads();
    for (int off = 1; off < 1024; off <<= 1) {
        int v = (t >= off) ? part[t - off] : 0;
        __syncthreads();
        part[t] += v;
        __syncthreads();
    }
    int run = (t == 0) ? 0 : part[t - 1];
    for (int i = lo; i < hi; i++) {
        g_rowstart[i] = run;
        g_cursor[i] = run;
        run += g_deg[i];
    }
    if (t == 1023) g_rowstart[N_NODES] = run;
}

__global__ void fill_kernel(const int* __restrict__ ei) {
    int e = blockIdx.x * blockDim.x + threadIdx.x;
    if (e >= N_EDGES) return;
    int dst = clampi(ei[N_EDGES + e]);
    int slot = atomicAdd(&g_cursor[dst], 1);
    g_csr[slot] = clampi(ei[e]);
}

// ---- gather1: mean of x over in-neighbors -> fp16 (warp per node) ----
__global__ void gather1_kernel(const float* __restrict__ x) {
    int node = (int)((blockIdx.x * (long)blockDim.x + threadIdx.x) >> 5);
    int lane = threadIdx.x & 31;
    if (node >= N_NODES) return;
    int s = g_rowstart[node], e = g_rowstart[node + 1];
    float acc[8];
#pragma unroll
    for (int j = 0; j < 8; j++) acc[j] = 0.f;
    for (int i = s; i < e; i++) {
        int src = g_csr[i];
        const float4* xr = (const float4*)(x + (long)src * D_IN);
        float4 a = xr[lane * 2], b = xr[lane * 2 + 1];
        acc[0] += a.x; acc[1] += a.y; acc[2] += a.z; acc[3] += a.w;
        acc[4] += b.x; acc[5] += b.y; acc[6] += b.z; acc[7] += b.w;
    }
    float r = 1.0f / fmaxf((float)(e - s), 1.0f);
    uint4 p = make_uint4(
        hpack(__float2half(acc[0] * r), __float2half(acc[1] * r)),
        hpack(__float2half(acc[2] * r), __float2half(acc[3] * r)),
        hpack(__float2half(acc[4] * r), __float2half(acc[5] * r)),
        hpack(__float2half(acc[6] * r), __float2half(acc[7] * r)));
    ((uint4*)(g_m1 + (long)node * D_IN))[lane] = p;
}

// ======================================================================
// fp16 single-pass tensor GEMM. Block 128x128, BK=32, 256 thr, 8 warps.
// 2-stage cp.async double buffer. SPAD=40 halves -> conflict-free ldsm.
// ======================================================================
#define GBM 128
#define GBN 128
#define GBK 32
#define SPAD 40

struct GemmSmem {
    __half A[GBM][SPAD];
    __half B[GBN][SPAD];
};
#define GEMM_SMEM_BYTES (2 * sizeof(GemmSmem))

__device__ __forceinline__ void cpa16(uint32_t dst, const void* src, int srcsize) {
    asm volatile("cp.async.cg.shared.global [%0], [%1], 16, %2;"
                 :: "r"(dst), "l"(src), "r"(srcsize));
}

__device__ __forceinline__ void ldsm_x4(uint32_t& r0, uint32_t& r1,
                                        uint32_t& r2, uint32_t& r3, uint32_t addr) {
    asm volatile("ldmatrix.sync.aligned.m8n8.x4.shared.b16 {%0,%1,%2,%3}, [%4];"
                 : "=r"(r0), "=r"(r1), "=r"(r2), "=r"(r3) : "r"(addr));
}

__device__ __forceinline__ void mma_fp16(float* d, const uint32_t* a,
                                         uint32_t b0, uint32_t b1) {
    asm volatile(
        "mma.sync.aligned.m16n8k16.row.col.f32.f16.f16.f32 "
        "{%0,%1,%2,%3}, {%4,%5,%6,%7}, {%8,%9}, {%0,%1,%2,%3};"
        : "+f"(d[0]), "+f"(d[1]), "+f"(d[2]), "+f"(d[3])
        : "r"(a[0]), "r"(a[1]), "r"(a[2]), "r"(a[3]), "r"(b0), "r"(b1));
}

// load one chunk: A[row0.., ka..ka+31] (stride asr), B rows coln0.. of Bt (stride bsr)
__device__ __forceinline__ void load_chunk(GemmSmem* sm,
        const __half* A, int row0, int ka, int asr,
        const __half* B, int coln0, int kb, int bsr) {
    uint32_t bA = (uint32_t)__cvta_generic_to_shared(&sm->A[0][0]);
    uint32_t bB = (uint32_t)__cvta_generic_to_shared(&sm->B[0][0]);
    int t = threadIdx.x;
#pragma unroll
    for (int p = 0; p < 2; p++) {
        int idx = t + p * 256;
        int row = idx >> 2, seg = idx & 3;
        uint32_t soff = (uint32_t)(row * SPAD + seg * 8) * 2;
        int grow = row0 + row;
        int pred = (grow < N_NODES) ? 16 : 0;
        long aoff = (long)min(grow, N_NODES - 1) * asr + ka + seg * 8;
        cpa16(bA + soff, A + aoff, pred);
        long boff = (long)(coln0 + row) * bsr + kb + seg * 8;
        cpa16(bB + soff, B + boff, 16);
    }
    asm volatile("cp.async.commit_group;");
}

__device__ __forceinline__ void mma_chunk(GemmSmem* sm, float acc[2][8][4],
                                          int wm, int wn, int lane) {
    uint32_t baseA = (uint32_t)__cvta_generic_to_shared(&sm->A[0][0]);
    uint32_t baseB = (uint32_t)__cvta_generic_to_shared(&sm->B[0][0]);
#pragma unroll
    for (int ks = 0; ks < 2; ks++) {
        uint32_t a[2][4];
#pragma unroll
        for (int mi = 0; mi < 2; mi++) {
            int row = wm * 32 + mi * 16 + (lane & 15);
            int col = ks * 16 + ((lane >> 4) << 3);
            uint32_t off = (uint32_t)(row * SPAD + col) * 2;
            ldsm_x4(a[mi][0], a[mi][1], a[mi][2], a[mi][3], baseA + off);
        }
#pragma unroll
        for (int nj = 0; nj < 4; nj++) {
            int row = wn * 64 + nj * 16 + ((lane >> 4) << 3) + (lane & 7);
            int col = ks * 16 + ((lane >> 3) & 1) * 8;
            uint32_t off = (uint32_t)(row * SPAD + col) * 2;
            uint32_t b0, b1, b2, b3;
            ldsm_x4(b0, b1, b2, b3, baseB + off);
#pragma unroll
            for (int mi = 0; mi < 2; mi++) {
                mma_fp16(acc[mi][nj * 2 + 0], a[mi], b0, b1);
                mma_fp16(acc[mi][nj * 2 + 1], a[mi], b2, b3);
            }
        }
    }
}

// h = relu([mean1|x] @ [W1l;W1r] + b1) -> fp16
__global__ __launch_bounds__(256, 2)
void gemm1_tc(const float* __restrict__ b1) {
    extern __shared__ __align__(16) char smraw[];
    GemmSmem* st = (GemmSmem*)smraw;
    float acc[2][8][4];
#pragma unroll
    for (int i = 0; i < 2; i++)
#pragma unroll
        for (int j = 0; j < 8; j++)
#pragma unroll
            for (int k = 0; k < 4; k++) acc[i][j][k] = 0.f;

    int lane = threadIdx.x & 31;
    int wid  = threadIdx.x >> 5;
    int wm = wid & 3, wn = wid >> 2;
    int row0 = blockIdx.x * GBM;
    int col0 = blockIdx.y * GBN;
    const int NC = 16;   // K = 512

    auto issue = [&](int c) {
        int k0 = c * GBK;
        const __half* As;
        int kk;
        if (k0 < 256) { As = g_m1; kk = k0; }
        else          { As = g_xf; kk = k0 - 256; }
        load_chunk(&st[c & 1], As, row0, kk, D_IN, g_w1, col0, k0, 2 * D_IN);
    };

    issue(0);
#pragma unroll 1
    for (int c = 0; c < NC; c++) {
        if (c + 1 < NC) {
            issue(c + 1);
            asm volatile("cp.async.wait_group 1;");
        } else {
            asm volatile("cp.async.wait_group 0;");
        }
        __syncthreads();
        mma_chunk(&st[c & 1], acc, wm, wn, lane);
        __syncthreads();
    }

    int g = lane >> 2, tg = lane & 3;
#pragma unroll
    for (int mi = 0; mi < 2; mi++) {
        int r = row0 + wm * 32 + mi * 16 + g;
#pragma unroll
        for (int t = 0; t < 8; t++) {
            int c = col0 + wn * 64 + t * 8 + tg * 2;
            float bb0 = b1[c], bb1 = b1[c + 1];
            if (r < N_NODES) {
                float v0 = fmaxf(acc[mi][t][0] + bb0, 0.f);
                float v1 = fmaxf(acc[mi][t][1] + bb1, 0.f);
                *(uint32_t*)(g_hf + (long)r * D_HID + c) =
                    hpack(__float2half(v0), __float2half(v1));
            }
            if (r + 8 < N_NODES) {
                float v0 = fmaxf(acc[mi][t][2] + bb0, 0.f);
                float v1 = fmaxf(acc[mi][t][3] + bb1, 0.f);
                *(uint32_t*)(g_hf + (long)(r + 8) * D_HID + c) =
                    hpack(__float2half(v0), __float2half(v1));
            }
        }
    }
}

// [y2|z2] = h @ [W2l|W2r] (+b2 on z2 half)
__global__ __launch_bounds__(256, 2)
void gemm2_tc(const float* __restrict__ b2) {
    extern __shared__ __align__(16) char smraw[];
    GemmSmem* st = (GemmSmem*)smraw;
    float acc[2][8][4];
#pragma unroll
    for (int i = 0; i < 2; i++)
#pragma unroll
        for (int j = 0; j < 8; j++)
#pragma unroll
            for (int k = 0; k < 4; k++) acc[i][j][k] = 0.f;

    int lane = threadIdx.x & 31;
    int wid  = threadIdx.x >> 5;
    int wm = wid & 3, wn = wid >> 2;
    int row0 = blockIdx.x * GBM;
    int col0 = blockIdx.y * GBN;
    const int NC = 8;    // K = 256

    auto issue = [&](int c) {
        int k0 = c * GBK;
        load_chunk(&st[c & 1], g_hf, row0, k0, D_HID, g_w2, col0, k0, D_HID);
    };

    issue(0);
#pragma unroll 1
    for (int c = 0; c < NC; c++) {
        if (c + 1 < NC) {
            issue(c + 1);
            asm volatile("cp.async.wait_group 1;");
        } else {
            asm volatile("cp.async.wait_group 0;");
        }
        __syncthreads();
        mma_chunk(&st[c & 1], acc, wm, wn, lane);
        __syncthreads();
    }

    int g = lane >> 2, tg = lane & 3;
#pragma unroll
    for (int mi = 0; mi < 2; mi++) {
        int r = row0 + wm * 32 + mi * 16 + g;
#pragma unroll
        for (int t = 0; t < 8; t++) {
            int cg = col0 + wn * 64 + t * 8 + tg * 2;   // 0..255
            bool zside = (cg >= 128);
            int cl = zside ? cg - 128 : cg;
            float bb0 = zside ? b2[cl] : 0.f;
            float bb1 = zside ? b2[cl + 1] : 0.f;
            float* C = zside ? g_z2 : g_y2;
            if (r < N_NODES) {
                float2 o = make_float2(acc[mi][t][0] + bb0, acc[mi][t][1] + bb1);
                *(float2*)(C + (long)r * D_OUT + cl) = o;
            }
            if (r + 8 < N_NODES) {
                float2 o = make_float2(acc[mi][t][2] + bb0, acc[mi][t][3] + bb1);
                *(float2*)(C + (long)(r + 8) * D_OUT + cl) = o;
            }
        }
    }
}

// ---- gather2 + final: out = mean(y2 over in-neighbors) + z2  (warp per node) ----
__global__ void gather2_final_kernel(float* __restrict__ out) {
    int node = (int)((blockIdx.x * (long)blockDim.x + threadIdx.x) >> 5);
    int lane = threadIdx.x & 31;
    if (node >= N_NODES) return;
    int s = g_rowstart[node], e = g_rowstart[node + 1];
    float a0 = 0.f, a1 = 0.f, a2 = 0.f, a3 = 0.f;
    for (int i = s; i < e; i++) {
        int src = g_csr[i];
        float4 v = ((const float4*)(g_y2 + (long)src * D_OUT))[lane];
        a0 += v.x; a1 += v.y; a2 += v.z; a3 += v.w;
    }
    float r = 1.0f / fmaxf((float)(e - s), 1.0f);
    float4 z = ((const float4*)(g_z2 + (long)node * D_OUT))[lane];
    float4 o;
    o.x = a0 * r + z.x;
    o.y = a1 * r + z.y;
    o.z = a2 * r + z.z;
    o.w = a3 * r + z.w;
    ((float4*)(out + (long)node * D_OUT))[lane] = o;
}

extern "C" void kernel_launch(void* const* d_in, const int* in_sizes, int n_in,
                              void* d_out, int out_size) {
    const float* x   = (const float*)d_in[0];
    const int*   ei  = (const int*)d_in[1];
    const float* W1l = (const float*)d_in[2];
    const float* b1  = (const float*)d_in[3];
    const float* W1r = (const float*)d_in[4];
    const float* W2l = (const float*)d_in[5];
    const float* b2  = (const float*)d_in[6];
    const float* W2r = (const float*)d_in[7];
    float* out = (float*)d_out;

    cudaFuncSetAttribute(gemm1_tc, cudaFuncAttributeMaxDynamicSharedMemorySize,
                         (int)GEMM_SMEM_BYTES);
    cudaFuncSetAttribute(gemm2_tc, cudaFuncAttributeMaxDynamicSharedMemorySize,
                         (int)GEMM_SMEM_BYTES);

    zero_deg_kernel<<<(N_NODES + 255) / 256, 256>>>();
    convert_x_kernel<<<(N_NODES * D_IN / 4 + 255) / 256, 256>>>(x);
    convert_w_kernel<<<768, 256>>>(W1l, W1r, W2l, W2r);
    degree_kernel<<<(N_EDGES + 255) / 256, 256>>>(ei);
    scan_kernel<<<1, 1024>>>();
    fill_kernel<<<(N_EDGES + 255) / 256, 256>>>(ei);
    gather1_kernel<<<(N_NODES * 32 + 255) / 256, 256>>>(x);

    gemm1_tc<<<dim3((N_NODES + GBM - 1) / GBM, 2), 256, GEMM_SMEM_BYTES>>>(b1);
    gemm2_tc<<<dim3((N_NODES + GBM - 1) / GBM, 2), 256, GEMM_SMEM_BYTES>>>(b2);

    gather2_final_kernel<<<(N_NODES * 32 + 255) / 256, 256>>>(out);
}

// round 9
// speedup vs baseline: 2.8995x; 1.1110x over previous
#include <cuda_runtime.h>
#include <cuda_fp16.h>
#include <cstdint>

#define N_NODES 50000
#define N_EDGES 800000
#define D_IN    256
#define D_HID   256
#define D_OUT   128

// ---- scratch (no allocations allowed) ----
__device__ __half g_xf [N_NODES * D_IN];    // fp16(x)
__device__ __half g_m1 [N_NODES * D_IN];    // fp16(mean1)
__device__ __half g_hf [N_NODES * D_HID];   // fp16(h)
__device__ __half g_w1 [D_HID * 2 * D_IN];  // B1^T: [256 n][512 k]
__device__ __half g_w2 [2 * D_OUT * D_HID]; // B2^T: [256 n][256 k]
__device__ __half g_y2f[N_NODES * D_OUT];   // fp16(h @ W2_l)
__device__ float g_z2[N_NODES * D_OUT];     // h @ W2_r + b2
__device__ int   g_deg[N_NODES];
__device__ int   g_rowstart[N_NODES + 1];
__device__ int   g_cursor[N_NODES];
__device__ int   g_csr[N_EDGES];

__device__ __forceinline__ int clampi(int v) {
    return min(max(v, 0), N_NODES - 1);
}

__device__ __forceinline__ uint32_t hpack(__half a, __half b) {
    union { __half2 v; uint32_t u; } t;
    t.v.x = a; t.v.y = b;
    return t.u;
}

// ---- per-launch reset (kernel_launch must be idempotent across calls!) ----
__global__ void zero_deg_kernel() {
    int i = blockIdx.x * blockDim.x + threadIdx.x;
    if (i < N_NODES) g_deg[i] = 0;
}

// ---- one-time conversions (pure functions of inputs) ----
__global__ void convert_x_kernel(const float* __restrict__ x) {
    long i = (long)blockIdx.x * blockDim.x + threadIdx.x;
    const long n = (long)N_NODES * D_IN / 4;
    if (i >= n) return;
    float4 v = ((const float4*)x)[i];
    ((uint2*)g_xf)[i] = make_uint2(hpack(__float2half(v.x), __float2half(v.y)),
                                   hpack(__float2half(v.z), __float2half(v.w)));
}

// transposed fp16 weight matrices
__global__ void convert_w_kernel(const float* __restrict__ W1l,
                                 const float* __restrict__ W1r,
                                 const float* __restrict__ W2l,
                                 const float* __restrict__ W2r) {
    int i = blockIdx.x * blockDim.x + threadIdx.x;
    const int n1 = D_HID * 2 * D_IN;       // 131072
    const int n2 = 2 * D_OUT * D_HID;      // 65536
    if (i < n1) {
        int n = i >> 9, k = i & 511;
        float v = (k < 256) ? W1l[k * D_HID + n] : W1r[(k - 256) * D_HID + n];
        g_w1[i] = __float2half(v);
    } else if (i < n1 + n2) {
        int j = i - n1;
        int n = j >> 8, k = j & 255;
        float v = (n < 128) ? W2l[k * D_OUT + n] : W2r[k * D_OUT + (n - 128)];
        g_w2[j] = __float2half(v);
    }
}

// ---- CSR build ----
__global__ void degree_kernel(const int* __restrict__ ei) {
    int e = blockIdx.x * blockDim.x + threadIdx.x;
    if (e < N_EDGES) atomicAdd(&g_deg[clampi(ei[N_EDGES + e])], 1);
}

__global__ void scan_kernel() {
    __shared__ int part[1024];
    int t = threadIdx.x;
    const int CH = (N_NODES + 1023) / 1024;  // 49
    int lo = t * CH, hi = min(lo + CH, N_NODES);
    int s = 0;
    for (int i = lo; i < hi; i++) s += g_deg[i];
    part[t] = s;
    __syncthreads();
    for (int off = 1; off < 1024; off <<= 1) {
        int v = (t >= off) ? part[t - off] : 0;
        __syncthreads();
        part[t] += v;
        __syncthreads();
    }
    int run = (t == 0) ? 0 : part[t - 1];
    for (int i = lo; i < hi; i++) {
        g_rowstart[i] = run;
        g_cursor[i] = run;
        run += g_deg[i];
    }
    if (t == 1023) g_rowstart[N_NODES] = run;
}

__global__ void fill_kernel(const int* __restrict__ ei) {
    int e = blockIdx.x * blockDim.x + threadIdx.x;
    if (e >= N_EDGES) return;
    int dst = clampi(ei[N_EDGES + e]);
    int slot = atomicAdd(&g_cursor[dst], 1);
    g_csr[slot] = clampi(ei[e]);
}

// ---- gather1: mean of fp16 x over in-neighbors -> fp16 (warp per node) ----
__global__ void gather1_kernel() {
    int node = (int)((blockIdx.x * (long)blockDim.x + threadIdx.x) >> 5);
    int lane = threadIdx.x & 31;
    if (node >= N_NODES) return;
    int s = g_rowstart[node], e = g_rowstart[node + 1];
    float acc[8];
#pragma unroll
    for (int j = 0; j < 8; j++) acc[j] = 0.f;
    for (int i = s; i < e; i++) {
        int src = g_csr[i];
        uint4 p = ((const uint4*)(g_xf + (long)src * D_IN))[lane];
        float2 f0 = __half22float2(*(__half2*)&p.x);
        float2 f1 = __half22float2(*(__half2*)&p.y);
        float2 f2 = __half22float2(*(__half2*)&p.z);
        float2 f3 = __half22float2(*(__half2*)&p.w);
        acc[0] += f0.x; acc[1] += f0.y; acc[2] += f1.x; acc[3] += f1.y;
        acc[4] += f2.x; acc[5] += f2.y; acc[6] += f3.x; acc[7] += f3.y;
    }
    float r = 1.0f / fmaxf((float)(e - s), 1.0f);
    uint4 p = make_uint4(
        hpack(__float2half(acc[0] * r), __float2half(acc[1] * r)),
        hpack(__float2half(acc[2] * r), __float2half(acc[3] * r)),
        hpack(__float2half(acc[4] * r), __float2half(acc[5] * r)),
        hpack(__float2half(acc[6] * r), __float2half(acc[7] * r)));
    ((uint4*)(g_m1 + (long)node * D_IN))[lane] = p;
}

// ======================================================================
// fp16 single-pass tensor GEMM. Block 128x128, BK=32, 256 thr, 8 warps.
// 2-stage cp.async double buffer. SPAD=40 halves -> conflict-free ldsm.
// ======================================================================
#define GBM 128
#define GBN 128
#define GBK 32
#define SPAD 40

struct GemmSmem {
    __half A[GBM][SPAD];
    __half B[GBN][SPAD];
};
#define GEMM_SMEM_BYTES (2 * sizeof(GemmSmem))

__device__ __forceinline__ void cpa16(uint32_t dst, const void* src, int srcsize) {
    asm volatile("cp.async.cg.shared.global [%0], [%1], 16, %2;"
                 :: "r"(dst), "l"(src), "r"(srcsize));
}

__device__ __forceinline__ void ldsm_x4(uint32_t& r0, uint32_t& r1,
                                        uint32_t& r2, uint32_t& r3, uint32_t addr) {
    asm volatile("ldmatrix.sync.aligned.m8n8.x4.shared.b16 {%0,%1,%2,%3}, [%4];"
                 : "=r"(r0), "=r"(r1), "=r"(r2), "=r"(r3) : "r"(addr));
}

__device__ __forceinline__ void mma_fp16(float* d, const uint32_t* a,
                                         uint32_t b0, uint32_t b1) {
    asm volatile(
        "mma.sync.aligned.m16n8k16.row.col.f32.f16.f16.f32 "
        "{%0,%1,%2,%3}, {%4,%5,%6,%7}, {%8,%9}, {%0,%1,%2,%3};"
        : "+f"(d[0]), "+f"(d[1]), "+f"(d[2]), "+f"(d[3])
        : "r"(a[0]), "r"(a[1]), "r"(a[2]), "r"(a[3]), "r"(b0), "r"(b1));
}

// load one chunk: A[row0.., ka..ka+31] (stride asr), B rows coln0.. of Bt (stride bsr)
__device__ __forceinline__ void load_chunk(GemmSmem* sm,
        const __half* A, int row0, int ka, int asr,
        const __half* B, int coln0, int kb, int bsr) {
    uint32_t bA = (uint32_t)__cvta_generic_to_shared(&sm->A[0][0]);
    uint32_t bB = (uint32_t)__cvta_generic_to_shared(&sm->B[0][0]);
    int t = threadIdx.x;
#pragma unroll
    for (int p = 0; p < 2; p++) {
        int idx = t + p * 256;
        int row = idx >> 2, seg = idx & 3;
        uint32_t soff = (uint32_t)(row * SPAD + seg * 8) * 2;
        int grow = row0 + row;
        int pred = (grow < N_NODES) ? 16 : 0;
        long aoff = (long)min(grow, N_NODES - 1) * asr + ka + seg * 8;
        cpa16(bA + soff, A + aoff, pred);
        long boff = (long)(coln0 + row) * bsr + kb + seg * 8;
        cpa16(bB + soff, B + boff, 16);
    }
    asm volatile("cp.async.commit_group;");
}

__device__ __forceinline__ void mma_chunk(GemmSmem* sm, float acc[2][8][4],
                                          int wm, int wn, int lane) {
    uint32_t baseA = (uint32_t)__cvta_generic_to_shared(&sm->A[0][0]);
    uint32_t baseB = (uint32_t)__cvta_generic_to_shared(&sm->B[0][0]);
#pragma unroll
    for (int ks = 0; ks < 2; ks++) {
        uint32_t a[2][4];
#pragma unroll
        for (int mi = 0; mi < 2; mi++) {
            int row = wm * 32 + mi * 16 + (lane & 15);
            int col = ks * 16 + ((lane >> 4) << 3);
            uint32_t off = (uint32_t)(row * SPAD + col) * 2;
            ldsm_x4(a[mi][0], a[mi][1], a[mi][2], a[mi][3], baseA + off);
        }
#pragma unroll
        for (int nj = 0; nj < 4; nj++) {
            int row = wn * 64 + nj * 16 + ((lane >> 4) << 3) + (lane & 7);
            int col = ks * 16 + ((lane >> 3) & 1) * 8;
            uint32_t off = (uint32_t)(row * SPAD + col) * 2;
            uint32_t b0, b1, b2, b3;
            ldsm_x4(b0, b1, b2, b3, baseB + off);
#pragma unroll
            for (int mi = 0; mi < 2; mi++) {
                mma_fp16(acc[mi][nj * 2 + 0], a[mi], b0, b1);
                mma_fp16(acc[mi][nj * 2 + 1], a[mi], b2, b3);
            }
        }
    }
}

// h = relu([mean1|x] @ [W1l;W1r] + b1) -> fp16
__global__ __launch_bounds__(256, 2)
void gemm1_tc(const float* __restrict__ b1) {
    extern __shared__ __align__(16) char smraw[];
    GemmSmem* st = (GemmSmem*)smraw;
    float acc[2][8][4];
#pragma unroll
    for (int i = 0; i < 2; i++)
#pragma unroll
        for (int j = 0; j < 8; j++)
#pragma unroll
            for (int k = 0; k < 4; k++) acc[i][j][k] = 0.f;

    int lane = threadIdx.x & 31;
    int wid  = threadIdx.x >> 5;
    int wm = wid & 3, wn = wid >> 2;
    int row0 = blockIdx.x * GBM;
    int col0 = blockIdx.y * GBN;
    const int NC = 16;   // K = 512

    auto issue = [&](int c) {
        int k0 = c * GBK;
        const __half* As;
        int kk;
        if (k0 < 256) { As = g_m1; kk = k0; }
        else          { As = g_xf; kk = k0 - 256; }
        load_chunk(&st[c & 1], As, row0, kk, D_IN, g_w1, col0, k0, 2 * D_IN);
    };

    issue(0);
#pragma unroll 1
    for (int c = 0; c < NC; c++) {
        if (c + 1 < NC) {
            issue(c + 1);
            asm volatile("cp.async.wait_group 1;");
        } else {
            asm volatile("cp.async.wait_group 0;");
        }
        __syncthreads();
        mma_chunk(&st[c & 1], acc, wm, wn, lane);
        __syncthreads();
    }

    int g = lane >> 2, tg = lane & 3;
#pragma unroll
    for (int mi = 0; mi < 2; mi++) {
        int r = row0 + wm * 32 + mi * 16 + g;
#pragma unroll
        for (int t = 0; t < 8; t++) {
            int c = col0 + wn * 64 + t * 8 + tg * 2;
            float bb0 = b1[c], bb1 = b1[c + 1];
            if (r < N_NODES) {
                float v0 = fmaxf(acc[mi][t][0] + bb0, 0.f);
                float v1 = fmaxf(acc[mi][t][1] + bb1, 0.f);
                *(uint32_t*)(g_hf + (long)r * D_HID + c) =
                    hpack(__float2half(v0), __float2half(v1));
            }
            if (r + 8 < N_NODES) {
                float v0 = fmaxf(acc[mi][t][2] + bb0, 0.f);
                float v1 = fmaxf(acc[mi][t][3] + bb1, 0.f);
                *(uint32_t*)(g_hf + (long)(r + 8) * D_HID + c) =
                    hpack(__float2half(v0), __float2half(v1));
            }
        }
    }
}

// [y2|z2] = h @ [W2l|W2r] (+b2 on z2 half); y2 stored fp16
__global__ __launch_bounds__(256, 2)
void gemm2_tc(const float* __restrict__ b2) {
    extern __shared__ __align__(16) char smraw[];
    GemmSmem* st = (GemmSmem*)smraw;
    float acc[2][8][4];
#pragma unroll
    for (int i = 0; i < 2; i++)
#pragma unroll
        for (int j = 0; j < 8; j++)
#pragma unroll
            for (int k = 0; k < 4; k++) acc[i][j][k] = 0.f;

    int lane = threadIdx.x & 31;
    int wid  = threadIdx.x >> 5;
    int wm = wid & 3, wn = wid >> 2;
    int row0 = blockIdx.x * GBM;
    int col0 = blockIdx.y * GBN;
    const int NC = 8;    // K = 256

    auto issue = [&](int c) {
        int k0 = c * GBK;
        load_chunk(&st[c & 1], g_hf, row0, k0, D_HID, g_w2, col0, k0, D_HID);
    };

    issue(0);
#pragma unroll 1
    for (int c = 0; c < NC; c++) {
        if (c + 1 < NC) {
            issue(c + 1);
            asm volatile("cp.async.wait_group 1;");
        } else {
            asm volatile("cp.async.wait_group 0;");
        }
        __syncthreads();
        mma_chunk(&st[c & 1], acc, wm, wn, lane);
        __syncthreads();
    }

    int g = lane >> 2, tg = lane & 3;
#pragma unroll
    for (int mi = 0; mi < 2; mi++) {
        int r = row0 + wm * 32 + mi * 16 + g;
#pragma unroll
        for (int t = 0; t < 8; t++) {
            int cg = col0 + wn * 64 + t * 8 + tg * 2;   // 0..255
            bool zside = (cg >= 128);
            int cl = zside ? cg - 128 : cg;
            if (!zside) {
                if (r < N_NODES)
                    *(uint32_t*)(g_y2f + (long)r * D_OUT + cl) =
                        hpack(__float2half(acc[mi][t][0]), __float2half(acc[mi][t][1]));
                if (r + 8 < N_NODES)
                    *(uint32_t*)(g_y2f + (long)(r + 8) * D_OUT + cl) =
                        hpack(__float2half(acc[mi][t][2]), __float2half(acc[mi][t][3]));
            } else {
                float bb0 = b2[cl], bb1 = b2[cl + 1];
                if (r < N_NODES) {
                    float2 o = make_float2(acc[mi][t][0] + bb0, acc[mi][t][1] + bb1);
                    *(float2*)(g_z2 + (long)r * D_OUT + cl) = o;
                }
                if (r + 8 < N_NODES) {
                    float2 o = make_float2(acc[mi][t][2] + bb0, acc[mi][t][3] + bb1);
                    *(float2*)(g_z2 + (long)(r + 8) * D_OUT + cl) = o;
                }
            }
        }
    }
}

// ---- gather2 + final: out = mean(fp16 y2 over in-neighbors) + z2 ----
__global__ void gather2_final_kernel(float* __restrict__ out) {
    int node = (int)((blockIdx.x * (long)blockDim.x + threadIdx.x) >> 5);
    int lane = threadIdx.x & 31;
    if (node >= N_NODES) return;
    int s = g_rowstart[node], e = g_rowstart[node + 1];
    float a0 = 0.f, a1 = 0.f, a2 = 0.f, a3 = 0.f;
    for (int i = s; i < e; i++) {
        int src = g_csr[i];
        uint2 p = ((const uint2*)(g_y2f + (long)src * D_OUT))[lane];
        float2 fa = __half22float2(*(__half2*)&p.x);
        float2 fb = __half22float2(*(__half2*)&p.y);
        a0 += fa.x; a1 += fa.y; a2 += fb.x; a3 += fb.y;
    }
    float r = 1.0f / fmaxf((float)(e - s), 1.0f);
    float4 z = ((const float4*)(g_z2 + (long)node * D_OUT))[lane];
    float4 o;
    o.x = a0 * r + z.x;
    o.y = a1 * r + z.y;
    o.z = a2 * r + z.z;
    o.w = a3 * r + z.w;
    ((float4*)(out + (long)node * D_OUT))[lane] = o;
}

extern "C" void kernel_launch(void* const* d_in, const int* in_sizes, int n_in,
                              void* d_out, int out_size) {
    const float* x   = (const float*)d_in[0];
    const int*   ei  = (const int*)d_in[1];
    const float* W1l = (const float*)d_in[2];
    const float* b1  = (const float*)d_in[3];
    const float* W1r = (const float*)d_in[4];
    const float* W2l = (const float*)d_in[5];
    const float* b2  = (const float*)d_in[6];
    const float* W2r = (const float*)d_in[7];
    float* out = (float*)d_out;

    cudaFuncSetAttribute(gemm1_tc, cudaFuncAttributeMaxDynamicSharedMemorySize,
                         (int)GEMM_SMEM_BYTES);
    cudaFuncSetAttribute(gemm2_tc, cudaFuncAttributeMaxDynamicSharedMemorySize,
                         (int)GEMM_SMEM_BYTES);

    zero_deg_kernel<<<(N_NODES + 255) / 256, 256>>>();
    convert_x_kernel<<<(N_NODES * D_IN / 4 + 255) / 256, 256>>>(x);
    convert_w_kernel<<<768, 256>>>(W1l, W1r, W2l, W2r);
    degree_kernel<<<(N_EDGES + 255) / 256, 256>>>(ei);
    scan_kernel<<<1, 1024>>>();
    fill_kernel<<<(N_EDGES + 255) / 256, 256>>>(ei);
    gather1_kernel<<<(N_NODES * 32 + 255) / 256, 256>>>();

    gemm1_tc<<<dim3((N_NODES + GBM - 1) / GBM, 2), 256, GEMM_SMEM_BYTES>>>(b1);
    gemm2_tc<<<dim3((N_NODES + GBM - 1) / GBM, 2), 256, GEMM_SMEM_BYTES>>>(b2);

    gather2_final_kernel<<<(N_NODES * 32 + 255) / 256, 256>>>(out);
}

// round 10
// speedup vs baseline: 3.0542x; 1.0534x over previous
#include <cuda_runtime.h>
#include <cuda_fp16.h>
#include <cstdint>

#define N_NODES 50000
#define N_EDGES 800000
#define D_IN    256
#define D_HID   256
#define D_OUT   128

// ---- scratch (no allocations allowed) ----
__device__ __half g_xf [N_NODES * D_IN];    // fp16(x)
__device__ __half g_m1 [N_NODES * D_IN];    // fp16(mean1)
__device__ __half g_hf [N_NODES * D_HID];   // fp16(h)
__device__ __half g_w1 [D_HID * 2 * D_IN];  // B1^T: [256 n][512 k]
__device__ __half g_w2 [2 * D_OUT * D_HID]; // B2^T: [256 n][256 k]
__device__ __half g_y2f[N_NODES * D_OUT];   // fp16(h @ W2_l)
__device__ float g_z2[N_NODES * D_OUT];     // h @ W2_r + b2
__device__ int   g_deg[N_NODES];
__device__ int   g_rowstart[N_NODES + 1];
__device__ int   g_cursor[N_NODES];
__device__ int   g_csr[N_EDGES];

__device__ __forceinline__ int clampi(int v) {
    return min(max(v, 0), N_NODES - 1);
}

__device__ __forceinline__ uint32_t hpack(__half a, __half b) {
    union { __half2 v; uint32_t u; } t;
    t.v.x = a; t.v.y = b;
    return t.u;
}

// ---- prep: zero g_deg + convert x + convert/transposed weights (one kernel) ----
__global__ void prep_kernel(const float* __restrict__ x,
                            const float* __restrict__ W1l,
                            const float* __restrict__ W1r,
                            const float* __restrict__ W2l,
                            const float* __restrict__ W2r) {
    int idx = blockIdx.x * blockDim.x + threadIdx.x;
    const int nx = N_NODES * D_IN / 4;     // 3,200,000 uint2 units
    if (idx < nx) {
        float4 v = ((const float4*)x)[idx];
        ((uint2*)g_xf)[idx] = make_uint2(
            hpack(__float2half(v.x), __float2half(v.y)),
            hpack(__float2half(v.z), __float2half(v.w)));
    }
    if (idx < N_NODES) g_deg[idx] = 0;
    const int n1 = D_HID * 2 * D_IN;       // 131072
    const int n2 = 2 * D_OUT * D_HID;      // 65536
    if (idx < n1) {
        int n = idx >> 9, k = idx & 511;
        float v = (k < 256) ? W1l[k * D_HID + n] : W1r[(k - 256) * D_HID + n];
        g_w1[idx] = __float2half(v);
    }
    if (idx < n2) {
        int n = idx >> 8, k = idx & 255;
        float v = (n < 128) ? W2l[k * D_OUT + n] : W2r[k * D_OUT + (n - 128)];
        g_w2[idx] = __float2half(v);
    }
}

// ---- CSR build ----
__global__ void degree_kernel(const int* __restrict__ ei) {
    int e = blockIdx.x * blockDim.x + threadIdx.x;
    if (e < N_EDGES) atomicAdd(&g_deg[clampi(ei[N_EDGES + e])], 1);
}

__global__ void scan_kernel() {
    __shared__ int part[1024];
    int t = threadIdx.x;
    const int CH = (N_NODES + 1023) / 1024;  // 49
    int lo = t * CH, hi = min(lo + CH, N_NODES);
    int s = 0;
    for (int i = lo; i < hi; i++) s += g_deg[i];
    part[t] = s;
    __syncthreads();
    for (int off = 1; off < 1024; off <<= 1) {
        int v = (t >= off) ? part[t - off] : 0;
        __syncthreads();
        part[t] += v;
        __syncthreads();
    }
    int run = (t == 0) ? 0 : part[t - 1];
    for (int i = lo; i < hi; i++) {
        g_rowstart[i] = run;
        g_cursor[i] = run;
        run += g_deg[i];
    }
    if (t == 1023) g_rowstart[N_NODES] = run;
}

__global__ void fill_kernel(const int* __restrict__ ei) {
    int e = blockIdx.x * blockDim.x + threadIdx.x;
    if (e >= N_EDGES) return;
    int dst = clampi(ei[N_EDGES + e]);
    int slot = atomicAdd(&g_cursor[dst], 1);
    g_csr[slot] = clampi(ei[e]);
}

// ---- gather1: mean of fp16 x over in-neighbors -> fp16 (warp per node, x4 unroll) ----
__device__ __forceinline__ void acc_row16(float* acc, const uint4& p) {
    float2 f0 = __half22float2(*(const __half2*)&p.x);
    float2 f1 = __half22float2(*(const __half2*)&p.y);
    float2 f2 = __half22float2(*(const __half2*)&p.z);
    float2 f3 = __half22float2(*(const __half2*)&p.w);
    acc[0] += f0.x; acc[1] += f0.y; acc[2] += f1.x; acc[3] += f1.y;
    acc[4] += f2.x; acc[5] += f2.y; acc[6] += f3.x; acc[7] += f3.y;
}

__global__ void gather1_kernel() {
    int node = (int)((blockIdx.x * (long)blockDim.x + threadIdx.x) >> 5);
    int lane = threadIdx.x & 31;
    if (node >= N_NODES) return;
    int s = g_rowstart[node], e = g_rowstart[node + 1];
    float acc[8];
#pragma unroll
    for (int j = 0; j < 8; j++) acc[j] = 0.f;
    int i = s;
    for (; i + 4 <= e; i += 4) {
        int s0 = g_csr[i], s1 = g_csr[i + 1], s2 = g_csr[i + 2], s3 = g_csr[i + 3];
        uint4 p0 = ((const uint4*)(g_xf + (long)s0 * D_IN))[lane];
        uint4 p1 = ((const uint4*)(g_xf + (long)s1 * D_IN))[lane];
        uint4 p2 = ((const uint4*)(g_xf + (long)s2 * D_IN))[lane];
        uint4 p3 = ((const uint4*)(g_xf + (long)s3 * D_IN))[lane];
        acc_row16(acc, p0); acc_row16(acc, p1);
        acc_row16(acc, p2); acc_row16(acc, p3);
    }
    for (; i < e; i++) {
        uint4 p = ((const uint4*)(g_xf + (long)g_csr[i] * D_IN))[lane];
        acc_row16(acc, p);
    }
    float r = 1.0f / fmaxf((float)(e - s), 1.0f);
    uint4 p = make_uint4(
        hpack(__float2half(acc[0] * r), __float2half(acc[1] * r)),
        hpack(__float2half(acc[2] * r), __float2half(acc[3] * r)),
        hpack(__float2half(acc[4] * r), __float2half(acc[5] * r)),
        hpack(__float2half(acc[6] * r), __float2half(acc[7] * r)));
    ((uint4*)(g_m1 + (long)node * D_IN))[lane] = p;
}

// ======================================================================
// fp16 single-pass tensor GEMM. Block 128x128, BK=32, 256 thr, 8 warps.
// 3-stage cp.async pipeline, ONE __syncthreads per iteration.
// ======================================================================
#define GBM 128
#define GBN 128
#define GBK 32
#define SPAD 40
#define NSTAGE 3

struct GemmSmem {
    __half A[GBM][SPAD];
    __half B[GBN][SPAD];
};
#define GEMM_SMEM_BYTES (NSTAGE * sizeof(GemmSmem))

__device__ __forceinline__ void cpa16(uint32_t dst, const void* src, int srcsize) {
    asm volatile("cp.async.cg.shared.global [%0], [%1], 16, %2;"
                 :: "r"(dst), "l"(src), "r"(srcsize));
}

__device__ __forceinline__ void ldsm_x4(uint32_t& r0, uint32_t& r1,
                                        uint32_t& r2, uint32_t& r3, uint32_t addr) {
    asm volatile("ldmatrix.sync.aligned.m8n8.x4.shared.b16 {%0,%1,%2,%3}, [%4];"
                 : "=r"(r0), "=r"(r1), "=r"(r2), "=r"(r3) : "r"(addr));
}

__device__ __forceinline__ void mma_fp16(float* d, const uint32_t* a,
                                         uint32_t b0, uint32_t b1) {
    asm volatile(
        "mma.sync.aligned.m16n8k16.row.col.f32.f16.f16.f32 "
        "{%0,%1,%2,%3}, {%4,%5,%6,%7}, {%8,%9}, {%0,%1,%2,%3};"
        : "+f"(d[0]), "+f"(d[1]), "+f"(d[2]), "+f"(d[3])
        : "r"(a[0]), "r"(a[1]), "r"(a[2]), "r"(a[3]), "r"(b0), "r"(b1));
}

// load one chunk: A[row0.., ka..ka+31] (stride asr), B rows coln0.. of Bt (stride bsr)
__device__ __forceinline__ void load_chunk(GemmSmem* sm,
        const __half* A, int row0, int ka, int asr,
        const __half* B, int coln0, int kb, int bsr) {
    uint32_t bA = (uint32_t)__cvta_generic_to_shared(&sm->A[0][0]);
    uint32_t bB = (uint32_t)__cvta_generic_to_shared(&sm->B[0][0]);
    int t = threadIdx.x;
#pragma unroll
    for (int p = 0; p < 2; p++) {
        int idx = t + p * 256;
        int row = idx >> 2, seg = idx & 3;
        uint32_t soff = (uint32_t)(row * SPAD + seg * 8) * 2;
        int grow = row0 + row;
        int pred = (grow < N_NODES) ? 16 : 0;
        long aoff = (long)min(grow, N_NODES - 1) * asr + ka + seg * 8;
        cpa16(bA + soff, A + aoff, pred);
        long boff = (long)(coln0 + row) * bsr + kb + seg * 8;
        cpa16(bB + soff, B + boff, 16);
    }
    asm volatile("cp.async.commit_group;");
}

__device__ __forceinline__ void mma_chunk(GemmSmem* sm, float acc[2][8][4],
                                          int wm, int wn, int lane) {
    uint32_t baseA = (uint32_t)__cvta_generic_to_shared(&sm->A[0][0]);
    uint32_t baseB = (uint32_t)__cvta_generic_to_shared(&sm->B[0][0]);
#pragma unroll
    for (int ks = 0; ks < 2; ks++) {
        uint32_t a[2][4];
#pragma unroll
        for (int mi = 0; mi < 2; mi++) {
            int row = wm * 32 + mi * 16 + (lane & 15);
            int col = ks * 16 + ((lane >> 4) << 3);
            uint32_t off = (uint32_t)(row * SPAD + col) * 2;
            ldsm_x4(a[mi][0], a[mi][1], a[mi][2], a[mi][3], baseA + off);
        }
#pragma unroll
        for (int nj = 0; nj < 4; nj++) {
            int row = wn * 64 + nj * 16 + ((lane >> 4) << 3) + (lane & 7);
            int col = ks * 16 + ((lane >> 3) & 1) * 8;
            uint32_t off = (uint32_t)(row * SPAD + col) * 2;
            uint32_t b0, b1, b2, b3;
            ldsm_x4(b0, b1, b2, b3, baseB + off);
#pragma unroll
            for (int mi = 0; mi < 2; mi++) {
                mma_fp16(acc[mi][nj * 2 + 0], a[mi], b0, b1);
                mma_fp16(acc[mi][nj * 2 + 1], a[mi], b2, b3);
            }
        }
    }
}

// h = relu([mean1|x] @ [W1l;W1r] + b1) -> fp16
__global__ __launch_bounds__(256, 2)
void gemm1_tc(const float* __restrict__ b1) {
    extern __shared__ __align__(16) char smraw[];
    GemmSmem* st = (GemmSmem*)smraw;
    float acc[2][8][4];
#pragma unroll
    for (int i = 0; i < 2; i++)
#pragma unroll
        for (int j = 0; j < 8; j++)
#pragma unroll
            for (int k = 0; k < 4; k++) acc[i][j][k] = 0.f;

    int lane = threadIdx.x & 31;
    int wid  = threadIdx.x >> 5;
    int wm = wid & 3, wn = wid >> 2;
    int row0 = blockIdx.x * GBM;
    int col0 = blockIdx.y * GBN;
    const int NC = 16;   // K = 512

    auto issue = [&](int c) {
        int k0 = c * GBK;
        const __half* As;
        int kk;
        if (k0 < 256) { As = g_m1; kk = k0; }
        else          { As = g_xf; kk = k0 - 256; }
        load_chunk(&st[c % NSTAGE], As, row0, kk, D_IN, g_w1, col0, k0, 2 * D_IN);
    };

    issue(0);
    issue(1);
#pragma unroll 1
    for (int c = 0; c < NC; c++) {
        if (c < NC - 1) asm volatile("cp.async.wait_group 1;");
        else            asm volatile("cp.async.wait_group 0;");
        __syncthreads();
        mma_chunk(&st[c % NSTAGE], acc, wm, wn, lane);
        if (c + 2 < NC) issue(c + 2);
    }

    int g = lane >> 2, tg = lane & 3;
#pragma unroll
    for (int mi = 0; mi < 2; mi++) {
        int r = row0 + wm * 32 + mi * 16 + g;
#pragma unroll
        for (int t = 0; t < 8; t++) {
            int c = col0 + wn * 64 + t * 8 + tg * 2;
            float bb0 = b1[c], bb1 = b1[c + 1];
            if (r < N_NODES) {
                float v0 = fmaxf(acc[mi][t][0] + bb0, 0.f);
                float v1 = fmaxf(acc[mi][t][1] + bb1, 0.f);
                *(uint32_t*)(g_hf + (long)r * D_HID + c) =
                    hpack(__float2half(v0), __float2half(v1));
            }
            if (r + 8 < N_NODES) {
                float v0 = fmaxf(acc[mi][t][2] + bb0, 0.f);
                float v1 = fmaxf(acc[mi][t][3] + bb1, 0.f);
                *(uint32_t*)(g_hf + (long)(r + 8) * D_HID + c) =
                    hpack(__float2half(v0), __float2half(v1));
            }
        }
    }
}

// [y2|z2] = h @ [W2l|W2r] (+b2 on z2 half); y2 stored fp16
__global__ __launch_bounds__(256, 2)
void gemm2_tc(const float* __restrict__ b2) {
    extern __shared__ __align__(16) char smraw[];
    GemmSmem* st = (GemmSmem*)smraw;
    float acc[2][8][4];
#pragma unroll
    for (int i = 0; i < 2; i++)
#pragma unroll
        for (int j = 0; j < 8; j++)
#pragma unroll
            for (int k = 0; k < 4; k++) acc[i][j][k] = 0.f;

    int lane = threadIdx.x & 31;
    int wid  = threadIdx.x >> 5;
    int wm = wid & 3, wn = wid >> 2;
    int row0 = blockIdx.x * GBM;
    int col0 = blockIdx.y * GBN;
    const int NC = 8;    // K = 256

    auto issue = [&](int c) {
        int k0 = c * GBK;
        load_chunk(&st[c % NSTAGE], g_hf, row0, k0, D_HID, g_w2, col0, k0, D_HID);
    };

    issue(0);
    issue(1);
#pragma unroll 1
    for (int c = 0; c < NC; c++) {
        if (c < NC - 1) asm volatile("cp.async.wait_group 1;");
        else            asm volatile("cp.async.wait_group 0;");
        __syncthreads();
        mma_chunk(&st[c % NSTAGE], acc, wm, wn, lane);
        if (c + 2 < NC) issue(c + 2);
    }

    int g = lane >> 2, tg = lane & 3;
#pragma unroll
    for (int mi = 0; mi < 2; mi++) {
        int r = row0 + wm * 32 + mi * 16 + g;
#pragma unroll
        for (int t = 0; t < 8; t++) {
            int cg = col0 + wn * 64 + t * 8 + tg * 2;   // 0..255
            bool zside = (cg >= 128);
            int cl = zside ? cg - 128 : cg;
            if (!zside) {
                if (r < N_NODES)
                    *(uint32_t*)(g_y2f + (long)r * D_OUT + cl) =
                        hpack(__float2half(acc[mi][t][0]), __float2half(acc[mi][t][1]));
                if (r + 8 < N_NODES)
                    *(uint32_t*)(g_y2f + (long)(r + 8) * D_OUT + cl) =
                        hpack(__float2half(acc[mi][t][2]), __float2half(acc[mi][t][3]));
            } else {
                float bb0 = b2[cl], bb1 = b2[cl + 1];
                if (r < N_NODES) {
                    float2 o = make_float2(acc[mi][t][0] + bb0, acc[mi][t][1] + bb1);
                    *(float2*)(g_z2 + (long)r * D_OUT + cl) = o;
                }
                if (r + 8 < N_NODES) {
                    float2 o = make_float2(acc[mi][t][2] + bb0, acc[mi][t][3] + bb1);
                    *(float2*)(g_z2 + (long)(r + 8) * D_OUT + cl) = o;
                }
            }
        }
    }
}

// ---- gather2 + final: out = mean(fp16 y2 over in-neighbors) + z2 (x4 unroll) ----
__device__ __forceinline__ void acc_row8(float& a0, float& a1, float& a2, float& a3,
                                         const uint2& p) {
    float2 fa = __half22float2(*(const __half2*)&p.x);
    float2 fb = __half22float2(*(const __half2*)&p.y);
    a0 += fa.x; a1 += fa.y; a2 += fb.x; a3 += fb.y;
}

__global__ void gather2_final_kernel(float* __restrict__ out) {
    int node = (int)((blockIdx.x * (long)blockDim.x + threadIdx.x) >> 5);
    int lane = threadIdx.x & 31;
    if (node >= N_NODES) return;
    int s = g_rowstart[node], e = g_rowstart[node + 1];
    float a0 = 0.f, a1 = 0.f, a2 = 0.f, a3 = 0.f;
    int i = s;
    for (; i + 4 <= e; i += 4) {
        int s0 = g_csr[i], s1 = g_csr[i + 1], s2 = g_csr[i + 2], s3 = g_csr[i + 3];
        uint2 p0 = ((const uint2*)(g_y2f + (long)s0 * D_OUT))[lane];
        uint2 p1 = ((const uint2*)(g_y2f + (long)s1 * D_OUT))[lane];
        uint2 p2 = ((const uint2*)(g_y2f + (long)s2 * D_OUT))[lane];
        uint2 p3 = ((const uint2*)(g_y2f + (long)s3 * D_OUT))[lane];
        acc_row8(a0, a1, a2, a3, p0); acc_row8(a0, a1, a2, a3, p1);
        acc_row8(a0, a1, a2, a3, p2); acc_row8(a0, a1, a2, a3, p3);
    }
    for (; i < e; i++) {
        uint2 p = ((const uint2*)(g_y2f + (long)g_csr[i] * D_OUT))[lane];
        acc_row8(a0, a1, a2, a3, p);
    }
    float r = 1.0f / fmaxf((float)(e - s), 1.0f);
    float4 z = ((const float4*)(g_z2 + (long)node * D_OUT))[lane];
    float4 o;
    o.x = a0 * r + z.x;
    o.y = a1 * r + z.y;
    o.z = a2 * r + z.z;
    o.w = a3 * r + z.w;
    ((float4*)(out + (long)node * D_OUT))[lane] = o;
}

extern "C" void kernel_launch(void* const* d_in, const int* in_sizes, int n_in,
                              void* d_out, int out_size) {
    const float* x   = (const float*)d_in[0];
    const int*   ei  = (const int*)d_in[1];
    const float* W1l = (const float*)d_in[2];
    const float* b1  = (const float*)d_in[3];
    const float* W1r = (const float*)d_in[4];
    const float* W2l = (const float*)d_in[5];
    const float* b2  = (const float*)d_in[6];
    const float* W2r = (const float*)d_in[7];
    float* out = (float*)d_out;

    cudaFuncSetAttribute(gemm1_tc, cudaFuncAttributeMaxDynamicSharedMemorySize,
                         (int)GEMM_SMEM_BYTES);
    cudaFuncSetAttribute(gemm2_tc, cudaFuncAttributeMaxDynamicSharedMemorySize,
                         (int)GEMM_SMEM_BYTES);

    prep_kernel<<<(N_NODES * D_IN / 4 + 255) / 256, 256>>>(x, W1l, W1r, W2l, W2r);
    degree_kernel<<<(N_EDGES + 255) / 256, 256>>>(ei);
    scan_kernel<<<1, 1024>>>();
    fill_kernel<<<(N_EDGES + 255) / 256, 256>>>(ei);
    gather1_kernel<<<(N_NODES * 32 + 255) / 256, 256>>>();

    gemm1_tc<<<dim3((N_NODES + GBM - 1) / GBM, 2), 256, GEMM_SMEM_BYTES>>>(b1);
    gemm2_tc<<<dim3((N_NODES + GBM - 1) / GBM, 2), 256, GEMM_SMEM_BYTES>>>(b2);

    gather2_final_kernel<<<(N_NODES * 32 + 255) / 256, 256>>>(out);
}